// round 2
// baseline (speedup 1.0000x reference)
#include <cuda_runtime.h>

#define N_NODES 50000
#define D_IN    256
#define D_H     256
#define D_OUT   128
#define MAX_E   1600000
#define MAX_EL  100000

// ---------------- scratch (device globals; no allocation) ----------------
__device__ int   g_is64;
__device__ int   g_src[MAX_E];
__device__ int   g_dst[MAX_E];
__device__ int   g_eli_a[MAX_EL];
__device__ int   g_eli_b[MAX_EL];
__device__ int   g_counts[N_NODES];
__device__ int   g_offsets[N_NODES + 1];
__device__ int   g_cursor[N_NODES];
__device__ float g_dis[N_NODES];
__device__ int   g_src_sorted[MAX_E];
__device__ float g_h1[N_NODES * D_H];    // x @ W1
__device__ float g_z1[N_NODES * D_H];    // relu(agg(h1)+b1)
__device__ float g_h2[N_NODES * D_OUT];  // z1 @ W2
__device__ float g_z2[N_NODES * D_OUT];  // agg(h2)+b2

// ---------------- index dtype detection + normalization ----------------
// If edge_index is really int64 (values < 2^31), every odd 32-bit word of the
// first row is zero. If it's int32 (JAX x64 disabled canonicalizes int64 ->
// int32), odd words are random node ids; 256 of them all being zero is
// impossible in practice.
__global__ void detect_kernel(const int* __restrict__ raw) {
    if (blockIdx.x == 0 && threadIdx.x == 0) {
        int all_zero = 1;
        for (int i = 0; i < 256; i++) {
            if (raw[2 * i + 1] != 0) { all_zero = 0; break; }
        }
        g_is64 = all_zero;
    }
}

__global__ void convert_edges_kernel(const void* __restrict__ raw, int E) {
    int i = blockIdx.x * blockDim.x + threadIdx.x;
    if (i >= E) return;
    if (g_is64) {
        const long long* p = (const long long*)raw;
        g_src[i] = (int)p[i];
        g_dst[i] = (int)p[E + i];
    } else {
        const int* p = (const int*)raw;
        g_src[i] = p[i];
        g_dst[i] = p[E + i];
    }
}

__global__ void convert_eli_kernel(const void* __restrict__ raw, int EL) {
    int i = blockIdx.x * blockDim.x + threadIdx.x;
    if (i >= EL) return;
    if (g_is64) {
        const long long* p = (const long long*)raw;
        g_eli_a[i] = (int)p[i];
        g_eli_b[i] = (int)p[EL + i];
    } else {
        const int* p = (const int*)raw;
        g_eli_a[i] = p[i];
        g_eli_b[i] = p[EL + i];
    }
}

// ---------------- graph preprocessing ----------------
__global__ void zero_counts_kernel() {
    int i = blockIdx.x * blockDim.x + threadIdx.x;
    if (i < N_NODES) g_counts[i] = 0;
}

__global__ void count_kernel(int E) {
    int i = blockIdx.x * blockDim.x + threadIdx.x;
    if (i < E) atomicAdd(&g_counts[g_dst[i]], 1);
}

__global__ void dis_kernel() {
    int i = blockIdx.x * blockDim.x + threadIdx.x;
    if (i < N_NODES) {
        // degree includes the self-loop
        g_dis[i] = rsqrtf((float)(g_counts[i] + 1));
    }
}

// single-block exclusive scan of g_counts -> g_offsets (n = N_NODES)
__global__ void scan_kernel(int n) {
    __shared__ int tmp[1024];
    __shared__ int carry;
    if (threadIdx.x == 0) carry = 0;
    __syncthreads();
    for (int base = 0; base < n; base += 1024) {
        int i = base + threadIdx.x;
        int v = (i < n) ? g_counts[i] : 0;
        tmp[threadIdx.x] = v;
        __syncthreads();
        for (int off = 1; off < 1024; off <<= 1) {
            int t = (threadIdx.x >= off) ? tmp[threadIdx.x - off] : 0;
            __syncthreads();
            tmp[threadIdx.x] += t;
            __syncthreads();
        }
        if (i < n) g_offsets[i] = carry + tmp[threadIdx.x] - v;
        __syncthreads();                 // everyone has read carry
        if (threadIdx.x == 1023) carry += tmp[1023];
        __syncthreads();
    }
    if (threadIdx.x == 0) g_offsets[n] = carry;
}

__global__ void copy_cursor_kernel() {
    int i = blockIdx.x * blockDim.x + threadIdx.x;
    if (i < N_NODES) g_cursor[i] = g_offsets[i];
}

__global__ void fill_kernel(int E) {
    int i = blockIdx.x * blockDim.x + threadIdx.x;
    if (i < E) {
        int s = g_src[i];
        int d = g_dst[i];
        int p = atomicAdd(&g_cursor[d], 1);
        g_src_sorted[p] = s;
    }
}

// ---------------- fp32 SGEMM: C[M,N] = A[M,K] @ B[K,N] ----------------
// BM=128, BN=128, BK=8, 256 threads, 8x8 per thread.
__global__ __launch_bounds__(256) void sgemm_kernel(
    const float* __restrict__ A, const float* __restrict__ B,
    float* __restrict__ C, int M, int N, int K)
{
    __shared__ float As[8][132];   // padded, stored transposed: As[k][m]
    __shared__ float Bs[8][128];

    const int tid = threadIdx.x;
    const int bm = blockIdx.y * 128;
    const int bn = blockIdx.x * 128;
    const int tx = tid % 16;       // 16 col-threads * 8 = 128
    const int ty = tid / 16;       // 16 row-threads * 8 = 128

    float acc[8][8];
    #pragma unroll
    for (int i = 0; i < 8; i++)
        #pragma unroll
        for (int j = 0; j < 8; j++) acc[i][j] = 0.f;

    // A loader mapping: thread t -> row t/2, k-offset (t&1)*4 (float4)
    const int a_m = tid >> 1;
    const int a_k = (tid & 1) * 4;
    // B loader mapping: thread t -> k t/32, col (t%32)*4 (float4)
    const int b_k = tid >> 5;
    const int b_n = (tid & 31) * 4;

    for (int k0 = 0; k0 < K; k0 += 8) {
        int am = bm + a_m;
        float4 av = (am < M)
            ? *(const float4*)&A[(long long)am * K + k0 + a_k]
            : make_float4(0.f, 0.f, 0.f, 0.f);
        As[a_k + 0][a_m] = av.x;
        As[a_k + 1][a_m] = av.y;
        As[a_k + 2][a_m] = av.z;
        As[a_k + 3][a_m] = av.w;

        float4 bv = *(const float4*)&B[(long long)(k0 + b_k) * N + bn + b_n];
        *(float4*)&Bs[b_k][b_n] = bv;

        __syncthreads();

        #pragma unroll
        for (int k = 0; k < 8; k++) {
            float4 a0 = *(const float4*)&As[k][ty * 8];
            float4 a1 = *(const float4*)&As[k][ty * 8 + 4];
            float4 b0 = *(const float4*)&Bs[k][tx * 8];
            float4 b1 = *(const float4*)&Bs[k][tx * 8 + 4];
            float ar[8] = {a0.x, a0.y, a0.z, a0.w, a1.x, a1.y, a1.z, a1.w};
            float br[8] = {b0.x, b0.y, b0.z, b0.w, b1.x, b1.y, b1.z, b1.w};
            #pragma unroll
            for (int i = 0; i < 8; i++)
                #pragma unroll
                for (int j = 0; j < 8; j++)
                    acc[i][j] += ar[i] * br[j];
        }
        __syncthreads();
    }

    #pragma unroll
    for (int i = 0; i < 8; i++) {
        int row = bm + ty * 8 + i;
        if (row < M) {
            float4 c0 = make_float4(acc[i][0], acc[i][1], acc[i][2], acc[i][3]);
            float4 c1 = make_float4(acc[i][4], acc[i][5], acc[i][6], acc[i][7]);
            *(float4*)&C[(long long)row * N + bn + tx * 8]     = c0;
            *(float4*)&C[(long long)row * N + bn + tx * 8 + 4] = c1;
        }
    }
}

// ---------------- aggregation ----------------
// Z[i] = f(sum_{s in N(i)} H[s]*dis[s]*dis[i] + H[i]*dis[i]^2 + b)
template<int D, bool RELU>
__global__ void agg_kernel(const float* __restrict__ H, float* __restrict__ Z,
                           const float* __restrict__ bias)
{
    const int node = blockIdx.x;
    const int t = threadIdx.x;     // blockDim.x == D
    const float di = g_dis[node];

    float acc = H[(long long)node * D + t] * di * di;   // self loop

    int e   = g_offsets[node];
    int end = g_offsets[node + 1];

    for (; e + 4 <= end; e += 4) {
        int s0 = g_src_sorted[e + 0];
        int s1 = g_src_sorted[e + 1];
        int s2 = g_src_sorted[e + 2];
        int s3 = g_src_sorted[e + 3];
        float n0 = g_dis[s0] * di;
        float n1 = g_dis[s1] * di;
        float n2 = g_dis[s2] * di;
        float n3 = g_dis[s3] * di;
        float h0 = H[(long long)s0 * D + t];
        float h1 = H[(long long)s1 * D + t];
        float h2 = H[(long long)s2 * D + t];
        float h3 = H[(long long)s3 * D + t];
        acc += h0 * n0;
        acc += h1 * n1;
        acc += h2 * n2;
        acc += h3 * n3;
    }
    for (; e < end; e++) {
        int s = g_src_sorted[e];
        acc += H[(long long)s * D + t] * (g_dis[s] * di);
    }

    float v = acc + bias[t];
    Z[(long long)node * D + t] = RELU ? fmaxf(v, 0.f) : v;
}

// ---------------- decode: y[e] = dot(z2[a], z2[b]) over 128 dims ----------------
__global__ void decode_kernel(const float* __restrict__ Z,
                              float* __restrict__ y, int EL)
{
    int gw   = (blockIdx.x * blockDim.x + threadIdx.x) >> 5;
    int lane = threadIdx.x & 31;
    if (gw >= EL) return;
    int a = g_eli_a[gw];
    int b = g_eli_b[gw];
    float4 za = *(const float4*)&Z[(long long)a * 128 + lane * 4];
    float4 zb = *(const float4*)&Z[(long long)b * 128 + lane * 4];
    float s = za.x * zb.x + za.y * zb.y + za.z * zb.z + za.w * zb.w;
    #pragma unroll
    for (int o = 16; o; o >>= 1) s += __shfl_down_sync(0xffffffffu, s, o);
    if (lane == 0) y[gw] = s;
}

// ---------------- launch ----------------
extern "C" void kernel_launch(void* const* d_in, const int* in_sizes, int n_in,
                              void* d_out, int out_size)
{
    const float* x   = (const float*)d_in[0];
    const void*  ei  = d_in[1];
    const void*  eli = d_in[2];
    const float* W1  = (const float*)d_in[3];
    const float* b1  = (const float*)d_in[4];
    const float* W2  = (const float*)d_in[5];
    const float* b2  = (const float*)d_in[6];
    float*       y   = (float*)d_out;

    const int E  = in_sizes[1] / 2;
    const int EL = in_sizes[2] / 2;

    float *h1p, *z1p, *h2p, *z2p;
    cudaGetSymbolAddress((void**)&h1p, g_h1);
    cudaGetSymbolAddress((void**)&z1p, g_z1);
    cudaGetSymbolAddress((void**)&h2p, g_h2);
    cudaGetSymbolAddress((void**)&z2p, g_z2);

    const int TB = 256;
    // --- index normalization (dtype-agnostic) ---
    detect_kernel<<<1, 32>>>((const int*)ei);
    convert_edges_kernel<<<(E + TB - 1) / TB, TB>>>(ei, E);
    convert_eli_kernel<<<(EL + TB - 1) / TB, TB>>>(eli, EL);

    // --- graph prep ---
    zero_counts_kernel<<<(N_NODES + TB - 1) / TB, TB>>>();
    count_kernel<<<(E + TB - 1) / TB, TB>>>(E);
    dis_kernel<<<(N_NODES + TB - 1) / TB, TB>>>();
    scan_kernel<<<1, 1024>>>(N_NODES);
    copy_cursor_kernel<<<(N_NODES + TB - 1) / TB, TB>>>();
    fill_kernel<<<(E + TB - 1) / TB, TB>>>(E);

    // --- layer 1 ---
    {
        dim3 grid(D_H / 128, (N_NODES + 127) / 128);
        sgemm_kernel<<<grid, 256>>>(x, W1, h1p, N_NODES, D_H, D_IN);
    }
    agg_kernel<D_H, true><<<N_NODES, D_H>>>(h1p, z1p, b1);

    // --- layer 2 ---
    {
        dim3 grid(D_OUT / 128, (N_NODES + 127) / 128);
        sgemm_kernel<<<grid, 256>>>(z1p, W2, h2p, N_NODES, D_OUT, D_H);
    }
    agg_kernel<D_OUT, false><<<N_NODES, D_OUT>>>(h2p, z2p, b2);

    // --- decode ---
    decode_kernel<<<(EL * 32 + TB - 1) / TB, TB>>>(z2p, y, EL);
}

// round 3
// speedup vs baseline: 1.3049x; 1.3049x over previous
#include <cuda_runtime.h>

#define N_NODES 50000
#define D_IN    256
#define D_H     256
#define D_OUT   128
#define MAX_E   1600000
#define MAX_EL  100000

// ---------------- scratch (device globals; no allocation) ----------------
__device__ int   g_is64;
__device__ int   g_src[MAX_E];
__device__ int   g_dst[MAX_E];
__device__ int   g_eli_a[MAX_EL];
__device__ int   g_eli_b[MAX_EL];
__device__ int   g_counts[N_NODES];
__device__ int   g_offsets[N_NODES + 1];
__device__ int   g_cursor[N_NODES];
__device__ float g_dis[N_NODES];
__device__ int   g_src_sorted[MAX_E];
__device__ float g_h1[N_NODES * D_H];    // x @ W1
__device__ float g_z1[N_NODES * D_H];    // relu(agg(h1)+b1)
__device__ float g_h2[N_NODES * D_OUT];  // z1 @ W2
__device__ float g_z2[N_NODES * D_OUT];  // agg(h2)+b2

// ---------------- index dtype detection + normalization ----------------
__global__ void detect_kernel(const int* __restrict__ raw) {
    if (blockIdx.x == 0 && threadIdx.x == 0) {
        int all_zero = 1;
        for (int i = 0; i < 256; i++) {
            if (raw[2 * i + 1] != 0) { all_zero = 0; break; }
        }
        g_is64 = all_zero;
    }
}

// convert + degree count fused (g_counts must be zeroed first)
__global__ void convert_edges_kernel(const void* __restrict__ raw, int E) {
    int i = blockIdx.x * blockDim.x + threadIdx.x;
    if (i >= E) return;
    int s, d;
    if (g_is64) {
        const long long* p = (const long long*)raw;
        s = (int)p[i]; d = (int)p[E + i];
    } else {
        const int* p = (const int*)raw;
        s = p[i]; d = p[E + i];
    }
    g_src[i] = s;
    g_dst[i] = d;
    atomicAdd(&g_counts[d], 1);
}

__global__ void convert_eli_kernel(const void* __restrict__ raw, int EL) {
    int i = blockIdx.x * blockDim.x + threadIdx.x;
    if (i >= EL) return;
    if (g_is64) {
        const long long* p = (const long long*)raw;
        g_eli_a[i] = (int)p[i];
        g_eli_b[i] = (int)p[EL + i];
    } else {
        const int* p = (const int*)raw;
        g_eli_a[i] = p[i];
        g_eli_b[i] = p[EL + i];
    }
}

// ---------------- graph preprocessing ----------------
__global__ void zero_counts_kernel() {
    int i = blockIdx.x * blockDim.x + threadIdx.x;
    if (i < N_NODES) g_counts[i] = 0;
}

__global__ void dis_kernel() {
    int i = blockIdx.x * blockDim.x + threadIdx.x;
    if (i < N_NODES) g_dis[i] = rsqrtf((float)(g_counts[i] + 1));
}

__global__ void scan_kernel(int n) {
    __shared__ int tmp[1024];
    __shared__ int carry;
    if (threadIdx.x == 0) carry = 0;
    __syncthreads();
    for (int base = 0; base < n; base += 1024) {
        int i = base + threadIdx.x;
        int v = (i < n) ? g_counts[i] : 0;
        tmp[threadIdx.x] = v;
        __syncthreads();
        for (int off = 1; off < 1024; off <<= 1) {
            int t = (threadIdx.x >= off) ? tmp[threadIdx.x - off] : 0;
            __syncthreads();
            tmp[threadIdx.x] += t;
            __syncthreads();
        }
        if (i < n) g_offsets[i] = carry + tmp[threadIdx.x] - v;
        __syncthreads();
        if (threadIdx.x == 1023) carry += tmp[1023];
        __syncthreads();
    }
    if (threadIdx.x == 0) g_offsets[n] = carry;
}

__global__ void copy_cursor_kernel() {
    int i = blockIdx.x * blockDim.x + threadIdx.x;
    if (i < N_NODES) g_cursor[i] = g_offsets[i];
}

__global__ void fill_kernel(int E) {
    int i = blockIdx.x * blockDim.x + threadIdx.x;
    if (i < E) {
        int s = g_src[i];
        int d = g_dst[i];
        int p = atomicAdd(&g_cursor[d], 1);
        g_src_sorted[p] = s;
    }
}

// ---------------- TF32 tensor-core GEMM: C[M,N] = A[M,K] @ B[K,N] ----------------
// Block tile 128x128, BK=32, 256 threads (8 warps as 4x2 grid of 32x64 warp tiles).
// mma.sync.aligned.m16n8k8.row.col.f32.tf32.tf32.f32
__device__ __forceinline__ unsigned f2tf32(float x) {
    unsigned u;
    asm("cvt.rna.tf32.f32 %0, %1;" : "=r"(u) : "f"(x));
    return u;
}

#define GBK 32
#define LDSM 136   // padded leading dim: bank = 8*c + r, conflict-free frag reads

__global__ __launch_bounds__(256) void mma_gemm_kernel(
    const float* __restrict__ A, const float* __restrict__ B,
    float* __restrict__ C, int M, int N, int K)
{
    __shared__ unsigned As[GBK][LDSM];   // [k][m] tf32 bits
    __shared__ unsigned Bs[GBK][LDSM];   // [k][n] tf32 bits

    const int tid  = threadIdx.x;
    const int lane = tid & 31;
    const int w    = tid >> 5;
    const int wm   = (w & 3) * 32;     // warp M offset in block
    const int wn   = (w >> 2) * 64;    // warp N offset in block
    const int bm   = blockIdx.y * 128;
    const int bn   = blockIdx.x * 128;
    const int r    = lane >> 2;        // groupID
    const int c    = lane & 3;         // threadID_in_group

    float acc[2][8][4];
    #pragma unroll
    for (int i = 0; i < 2; i++)
        #pragma unroll
        for (int j = 0; j < 8; j++)
            #pragma unroll
            for (int q = 0; q < 4; q++) acc[i][j][q] = 0.f;

    // A staging: thread -> row am (0..127), k-quads {akq, akq+2, akq+4, akq+6}
    const int am  = tid & 127;
    const int akq = tid >> 7;          // 0 or 1
    // B staging: thread -> k-row bk (0..31), n-quads {bnq, bnq+8, bnq+16, bnq+24}
    const int bk  = tid >> 3;
    const int bnq = tid & 7;

    const int amg = bm + am;           // global A row
    const bool arow_ok = (amg < M);

    float4 sa[4], sb[4];
    const int ntiles = K / GBK;

    // prologue: load tile 0
    #pragma unroll
    for (int i = 0; i < 4; i++) {
        int k4 = (akq + i * 2) * 4;
        sa[i] = arow_ok ? *(const float4*)&A[(long long)amg * K + k4]
                        : make_float4(0.f, 0.f, 0.f, 0.f);
        int n4 = (bnq + i * 8) * 4;
        sb[i] = *(const float4*)&B[(long long)bk * N + bn + n4];
    }

    for (int kt = 0; kt < ntiles; kt++) {
        __syncthreads();
        // store staged tile to smem (convert to tf32)
        #pragma unroll
        for (int i = 0; i < 4; i++) {
            int k4 = (akq + i * 2) * 4;
            As[k4 + 0][am] = f2tf32(sa[i].x);
            As[k4 + 1][am] = f2tf32(sa[i].y);
            As[k4 + 2][am] = f2tf32(sa[i].z);
            As[k4 + 3][am] = f2tf32(sa[i].w);
            int n4 = (bnq + i * 8) * 4;
            uint4 bv;
            bv.x = f2tf32(sb[i].x); bv.y = f2tf32(sb[i].y);
            bv.z = f2tf32(sb[i].z); bv.w = f2tf32(sb[i].w);
            *(uint4*)&Bs[bk][n4] = bv;
        }
        __syncthreads();

        // prefetch next tile into regs (overlaps with MMA compute below)
        if (kt + 1 < ntiles) {
            int k0 = (kt + 1) * GBK;
            #pragma unroll
            for (int i = 0; i < 4; i++) {
                int k4 = (akq + i * 2) * 4;
                sa[i] = arow_ok ? *(const float4*)&A[(long long)amg * K + k0 + k4]
                                : make_float4(0.f, 0.f, 0.f, 0.f);
                int n4 = (bnq + i * 8) * 4;
                sb[i] = *(const float4*)&B[(long long)(k0 + bk) * N + bn + n4];
            }
        }

        // compute: 4 k8-steps over this tile
        #pragma unroll
        for (int kk = 0; kk < GBK; kk += 8) {
            unsigned af[2][4];
            #pragma unroll
            for (int tm = 0; tm < 2; tm++) {
                int mb = wm + tm * 16;
                af[tm][0] = As[kk + c    ][mb + r    ];
                af[tm][1] = As[kk + c    ][mb + r + 8];
                af[tm][2] = As[kk + c + 4][mb + r    ];
                af[tm][3] = As[kk + c + 4][mb + r + 8];
            }
            unsigned bf[8][2];
            #pragma unroll
            for (int tn = 0; tn < 8; tn++) {
                int nb = wn + tn * 8 + r;
                bf[tn][0] = Bs[kk + c    ][nb];
                bf[tn][1] = Bs[kk + c + 4][nb];
            }
            #pragma unroll
            for (int tm = 0; tm < 2; tm++)
                #pragma unroll
                for (int tn = 0; tn < 8; tn++) {
                    asm volatile(
                        "mma.sync.aligned.m16n8k8.row.col.f32.tf32.tf32.f32 "
                        "{%0,%1,%2,%3}, {%4,%5,%6,%7}, {%8,%9}, {%0,%1,%2,%3};"
                        : "+f"(acc[tm][tn][0]), "+f"(acc[tm][tn][1]),
                          "+f"(acc[tm][tn][2]), "+f"(acc[tm][tn][3])
                        : "r"(af[tm][0]), "r"(af[tm][1]),
                          "r"(af[tm][2]), "r"(af[tm][3]),
                          "r"(bf[tn][0]), "r"(bf[tn][1]));
                }
        }
    }

    // epilogue
    #pragma unroll
    for (int tm = 0; tm < 2; tm++) {
        int row0 = bm + wm + tm * 16 + r;
        #pragma unroll
        for (int tn = 0; tn < 8; tn++) {
            int col = bn + wn + tn * 8 + c * 2;
            if (row0 < M) {
                float2 v = make_float2(acc[tm][tn][0], acc[tm][tn][1]);
                *(float2*)&C[(long long)row0 * N + col] = v;
            }
            if (row0 + 8 < M) {
                float2 v = make_float2(acc[tm][tn][2], acc[tm][tn][3]);
                *(float2*)&C[(long long)(row0 + 8) * N + col] = v;
            }
        }
    }
}

// ---------------- aggregation ----------------
// Z[i] = f(sum_{s in N(i)} H[s]*dis[s]*dis[i] + H[i]*dis[i]^2 + b)
template<int D, bool RELU>
__global__ void agg_kernel(const float* __restrict__ H, float* __restrict__ Z,
                           const float* __restrict__ bias)
{
    const int node = blockIdx.x;
    const int t = threadIdx.x;     // blockDim.x == D
    const float di = g_dis[node];

    float acc = H[(long long)node * D + t] * di * di;   // self loop

    int e   = g_offsets[node];
    int end = g_offsets[node + 1];

    for (; e + 4 <= end; e += 4) {
        int s0 = g_src_sorted[e + 0];
        int s1 = g_src_sorted[e + 1];
        int s2 = g_src_sorted[e + 2];
        int s3 = g_src_sorted[e + 3];
        float n0 = g_dis[s0] * di;
        float n1 = g_dis[s1] * di;
        float n2 = g_dis[s2] * di;
        float n3 = g_dis[s3] * di;
        float h0 = H[(long long)s0 * D + t];
        float h1 = H[(long long)s1 * D + t];
        float h2 = H[(long long)s2 * D + t];
        float h3 = H[(long long)s3 * D + t];
        acc += h0 * n0;
        acc += h1 * n1;
        acc += h2 * n2;
        acc += h3 * n3;
    }
    for (; e < end; e++) {
        int s = g_src_sorted[e];
        acc += H[(long long)s * D + t] * (g_dis[s] * di);
    }

    float v = acc + bias[t];
    Z[(long long)node * D + t] = RELU ? fmaxf(v, 0.f) : v;
}

// ---------------- decode: y[e] = dot(z2[a], z2[b]) over 128 dims ----------------
__global__ void decode_kernel(const float* __restrict__ Z,
                              float* __restrict__ y, int EL)
{
    int gw   = (blockIdx.x * blockDim.x + threadIdx.x) >> 5;
    int lane = threadIdx.x & 31;
    if (gw >= EL) return;
    int a = g_eli_a[gw];
    int b = g_eli_b[gw];
    float4 za = *(const float4*)&Z[(long long)a * 128 + lane * 4];
    float4 zb = *(const float4*)&Z[(long long)b * 128 + lane * 4];
    float s = za.x * zb.x + za.y * zb.y + za.z * zb.z + za.w * zb.w;
    #pragma unroll
    for (int o = 16; o; o >>= 1) s += __shfl_down_sync(0xffffffffu, s, o);
    if (lane == 0) y[gw] = s;
}

// ---------------- launch ----------------
extern "C" void kernel_launch(void* const* d_in, const int* in_sizes, int n_in,
                              void* d_out, int out_size)
{
    const float* x   = (const float*)d_in[0];
    const void*  ei  = d_in[1];
    const void*  eli = d_in[2];
    const float* W1  = (const float*)d_in[3];
    const float* b1  = (const float*)d_in[4];
    const float* W2  = (const float*)d_in[5];
    const float* b2  = (const float*)d_in[6];
    float*       y   = (float*)d_out;

    const int E  = in_sizes[1] / 2;
    const int EL = in_sizes[2] / 2;

    float *h1p, *z1p, *h2p, *z2p;
    cudaGetSymbolAddress((void**)&h1p, g_h1);
    cudaGetSymbolAddress((void**)&z1p, g_z1);
    cudaGetSymbolAddress((void**)&h2p, g_h2);
    cudaGetSymbolAddress((void**)&z2p, g_z2);

    const int TB = 256;
    // --- prep ---
    zero_counts_kernel<<<(N_NODES + TB - 1) / TB, TB>>>();
    detect_kernel<<<1, 32>>>((const int*)ei);
    convert_edges_kernel<<<(E + TB - 1) / TB, TB>>>(ei, E);   // + degree count
    convert_eli_kernel<<<(EL + TB - 1) / TB, TB>>>(eli, EL);
    dis_kernel<<<(N_NODES + TB - 1) / TB, TB>>>();
    scan_kernel<<<1, 1024>>>(N_NODES);
    copy_cursor_kernel<<<(N_NODES + TB - 1) / TB, TB>>>();
    fill_kernel<<<(E + TB - 1) / TB, TB>>>(E);

    // --- layer 1 ---
    {
        dim3 grid(D_H / 128, (N_NODES + 127) / 128);
        mma_gemm_kernel<<<grid, 256>>>(x, W1, h1p, N_NODES, D_H, D_IN);
    }
    agg_kernel<D_H, true><<<N_NODES, D_H>>>(h1p, z1p, b1);

    // --- layer 2 ---
    {
        dim3 grid(D_OUT / 128, (N_NODES + 127) / 128);
        mma_gemm_kernel<<<grid, 256>>>(z1p, W2, h2p, N_NODES, D_OUT, D_H);
    }
    agg_kernel<D_OUT, false><<<N_NODES, D_OUT>>>(h2p, z2p, b2);

    // --- decode ---
    decode_kernel<<<(EL * 32 + TB - 1) / TB, TB>>>(z2p, y, EL);
}

// round 5
// speedup vs baseline: 2.0787x; 1.5929x over previous
#include <cuda_runtime.h>
#include <cuda_fp16.h>

#define N_NODES 50000
#define D_IN    256
#define D_H     256
#define D_OUT   128
#define MAX_E   1600000
#define MAX_EL  100000

// ---------------- scratch (device globals; no allocation) ----------------
__device__ int    g_is64;
__device__ int    g_src[MAX_E];
__device__ int    g_dst[MAX_E];
__device__ int    g_counts[N_NODES];
__device__ int    g_offsets[N_NODES + 1];
__device__ int    g_cursor[N_NODES];
__device__ float  g_dis[N_NODES];
__device__ int    g_src_sorted[MAX_E];
__device__ __half g_hh1[N_NODES * D_H];    // half(dis[i] * (x@W1)[i])
__device__ float  g_z1[N_NODES * D_H];     // relu(agg + b1)  (fp32, GEMM2 A operand)
__device__ __half g_hh2[N_NODES * D_OUT];  // half(dis[i] * (z1@W2)[i])
__device__ float  g_z2[N_NODES * D_OUT];   // agg + b2        (fp32, decode operand)

// ---------------- index dtype detection ----------------
__global__ void detect_kernel(const int* __restrict__ raw) {
    if (blockIdx.x == 0 && threadIdx.x == 0) {
        int all_zero = 1;
        for (int i = 0; i < 256; i++) {
            if (raw[2 * i + 1] != 0) { all_zero = 0; break; }
        }
        g_is64 = all_zero;
    }
}

__global__ void zero_counts_kernel() {
    int i = blockIdx.x * blockDim.x + threadIdx.x;
    if (i < N_NODES) g_counts[i] = 0;
}

// convert + degree count fused (g_counts zeroed first)
__global__ void convert_edges_kernel(const void* __restrict__ raw, int E) {
    int i = blockIdx.x * blockDim.x + threadIdx.x;
    if (i >= E) return;
    int s, d;
    if (g_is64) {
        const long long* p = (const long long*)raw;
        s = (int)p[i]; d = (int)p[E + i];
    } else {
        const int* p = (const int*)raw;
        s = p[i]; d = p[E + i];
    }
    g_src[i] = s;
    g_dst[i] = d;
    atomicAdd(&g_counts[d], 1);
}

__global__ void dis_kernel() {
    int i = blockIdx.x * blockDim.x + threadIdx.x;
    if (i < N_NODES) g_dis[i] = rsqrtf((float)(g_counts[i] + 1));
}

// exclusive scan of g_counts -> g_offsets (+ g_cursor copy)
__global__ void scan_kernel(int n) {
    __shared__ int tmp[1024];
    __shared__ int carry;
    if (threadIdx.x == 0) carry = 0;
    __syncthreads();
    for (int base = 0; base < n; base += 1024) {
        int i = base + threadIdx.x;
        int v = (i < n) ? g_counts[i] : 0;
        tmp[threadIdx.x] = v;
        __syncthreads();
        for (int off = 1; off < 1024; off <<= 1) {
            int t = (threadIdx.x >= off) ? tmp[threadIdx.x - off] : 0;
            __syncthreads();
            tmp[threadIdx.x] += t;
            __syncthreads();
        }
        if (i < n) {
            int excl = carry + tmp[threadIdx.x] - v;
            g_offsets[i] = excl;
            g_cursor[i]  = excl;
        }
        __syncthreads();
        if (threadIdx.x == 1023) carry += tmp[1023];
        __syncthreads();
    }
    if (threadIdx.x == 0) g_offsets[n] = carry;
}

__global__ void fill_kernel(int E) {
    int i = blockIdx.x * blockDim.x + threadIdx.x;
    if (i < E) {
        int p = atomicAdd(&g_cursor[g_dst[i]], 1);
        g_src_sorted[p] = g_src[i];
    }
}

// ---------------- TF32 tensor-core GEMM with fused scale+half epilogue ----------------
// C_half[row][col] = half( dis[row] * (A @ B)[row][col] )
__device__ __forceinline__ unsigned f2tf32(float x) {
    unsigned u;
    asm("cvt.rna.tf32.f32 %0, %1;" : "=r"(u) : "f"(x));
    return u;
}

#define GBK 32
#define LDSM 136   // padded leading dim: conflict-free fragment reads

__global__ __launch_bounds__(256) void mma_gemm_kernel(
    const float* __restrict__ A, const float* __restrict__ B,
    __half* __restrict__ Ch, const float* __restrict__ dis,
    int M, int N, int K)
{
    __shared__ unsigned As[GBK][LDSM];   // [k][m]
    __shared__ unsigned Bs[GBK][LDSM];   // [k][n]

    const int tid  = threadIdx.x;
    const int lane = tid & 31;
    const int w    = tid >> 5;
    const int wm   = (w & 3) * 32;
    const int wn   = (w >> 2) * 64;
    const int bm   = blockIdx.y * 128;
    const int bn   = blockIdx.x * 128;
    const int r    = lane >> 2;
    const int c    = lane & 3;

    float acc[2][8][4];
    #pragma unroll
    for (int i = 0; i < 2; i++)
        #pragma unroll
        for (int j = 0; j < 8; j++)
            #pragma unroll
            for (int q = 0; q < 4; q++) acc[i][j][q] = 0.f;

    const int am  = tid & 127;
    const int akq = tid >> 7;
    const int bk  = tid >> 3;
    const int bnq = tid & 7;

    const int amg = bm + am;
    const bool arow_ok = (amg < M);

    float4 sa[4], sb[4];
    const int ntiles = K / GBK;

    #pragma unroll
    for (int i = 0; i < 4; i++) {
        int k4 = (akq + i * 2) * 4;
        sa[i] = arow_ok ? *(const float4*)&A[(long long)amg * K + k4]
                        : make_float4(0.f, 0.f, 0.f, 0.f);
        int n4 = (bnq + i * 8) * 4;
        sb[i] = *(const float4*)&B[(long long)bk * N + bn + n4];
    }

    for (int kt = 0; kt < ntiles; kt++) {
        __syncthreads();
        #pragma unroll
        for (int i = 0; i < 4; i++) {
            int k4 = (akq + i * 2) * 4;
            As[k4 + 0][am] = f2tf32(sa[i].x);
            As[k4 + 1][am] = f2tf32(sa[i].y);
            As[k4 + 2][am] = f2tf32(sa[i].z);
            As[k4 + 3][am] = f2tf32(sa[i].w);
            int n4 = (bnq + i * 8) * 4;
            uint4 bv;
            bv.x = f2tf32(sb[i].x); bv.y = f2tf32(sb[i].y);
            bv.z = f2tf32(sb[i].z); bv.w = f2tf32(sb[i].w);
            *(uint4*)&Bs[bk][n4] = bv;
        }
        __syncthreads();

        if (kt + 1 < ntiles) {
            int k0 = (kt + 1) * GBK;
            #pragma unroll
            for (int i = 0; i < 4; i++) {
                int k4 = (akq + i * 2) * 4;
                sa[i] = arow_ok ? *(const float4*)&A[(long long)amg * K + k0 + k4]
                                : make_float4(0.f, 0.f, 0.f, 0.f);
                int n4 = (bnq + i * 8) * 4;
                sb[i] = *(const float4*)&B[(long long)(k0 + bk) * N + bn + n4];
            }
        }

        #pragma unroll
        for (int kk = 0; kk < GBK; kk += 8) {
            unsigned af[2][4];
            #pragma unroll
            for (int tm = 0; tm < 2; tm++) {
                int mb = wm + tm * 16;
                af[tm][0] = As[kk + c    ][mb + r    ];
                af[tm][1] = As[kk + c    ][mb + r + 8];
                af[tm][2] = As[kk + c + 4][mb + r    ];
                af[tm][3] = As[kk + c + 4][mb + r + 8];
            }
            unsigned bf[8][2];
            #pragma unroll
            for (int tn = 0; tn < 8; tn++) {
                int nb = wn + tn * 8 + r;
                bf[tn][0] = Bs[kk + c    ][nb];
                bf[tn][1] = Bs[kk + c + 4][nb];
            }
            #pragma unroll
            for (int tm = 0; tm < 2; tm++)
                #pragma unroll
                for (int tn = 0; tn < 8; tn++) {
                    asm volatile(
                        "mma.sync.aligned.m16n8k8.row.col.f32.tf32.tf32.f32 "
                        "{%0,%1,%2,%3}, {%4,%5,%6,%7}, {%8,%9}, {%0,%1,%2,%3};"
                        : "+f"(acc[tm][tn][0]), "+f"(acc[tm][tn][1]),
                          "+f"(acc[tm][tn][2]), "+f"(acc[tm][tn][3])
                        : "r"(af[tm][0]), "r"(af[tm][1]),
                          "r"(af[tm][2]), "r"(af[tm][3]),
                          "r"(bf[tn][0]), "r"(bf[tn][1]));
                }
        }
    }

    // fused epilogue: scale by dis[row], convert to half
    #pragma unroll
    for (int tm = 0; tm < 2; tm++) {
        int row0 = bm + wm + tm * 16 + r;
        int row1 = row0 + 8;
        float s0 = (row0 < M) ? dis[row0] : 0.f;
        float s1 = (row1 < M) ? dis[row1] : 0.f;
        #pragma unroll
        for (int tn = 0; tn < 8; tn++) {
            int col = bn + wn + tn * 8 + c * 2;
            if (row0 < M) {
                __half2 hv = __floats2half2_rn(acc[tm][tn][0] * s0,
                                               acc[tm][tn][1] * s0);
                *(__half2*)&Ch[(long long)row0 * N + col] = hv;
            }
            if (row1 < M) {
                __half2 hv = __floats2half2_rn(acc[tm][tn][2] * s1,
                                               acc[tm][tn][3] * s1);
                *(__half2*)&Ch[(long long)row1 * N + col] = hv;
            }
        }
    }
}

// ---------------- aggregation (half gathers, pre-scaled) ----------------
// z[i] = f( di * ( hh[i] + sum_{s in N(i)} hh[s] ) + b )   where hh = h*dis
// self term: di * hh[i] = h[i]*dis[i]^2  (reference self-loop)   <-- R4 bug was an extra *di here
template<int D, bool RELU>
__global__ __launch_bounds__(256) void agg_half_kernel(
    const __half* __restrict__ HH, float* __restrict__ Z,
    const float* __restrict__ bias)
{
    constexpr int TPN = D / 4;          // threads per node (half4 each)
    constexpr int NPB = 256 / TPN;      // nodes per block
    const int node = blockIdx.x * NPB + threadIdx.x / TPN;
    const int t    = threadIdx.x % TPN; // feature quad index
    if (node >= N_NODES) return;

    const float di = g_dis[node];
    const uint2* Hq = (const uint2*)HH; // row = TPN quads

    // self loop contributes hh[node] to acc (final *di outside makes it h*di^2)
    uint2 sv = Hq[(long long)node * TPN + t];
    float2 s0 = __half22float2(*(__half2*)&sv.x);
    float2 s1 = __half22float2(*(__half2*)&sv.y);
    float a0 = s0.x, a1 = s0.y, a2 = s1.x, a3 = s1.y;

    int e   = g_offsets[node];
    int end = g_offsets[node + 1];

    for (; e + 4 <= end; e += 4) {
        int n0 = g_src_sorted[e + 0];
        int n1 = g_src_sorted[e + 1];
        int n2 = g_src_sorted[e + 2];
        int n3 = g_src_sorted[e + 3];
        uint2 v0 = Hq[(long long)n0 * TPN + t];
        uint2 v1 = Hq[(long long)n1 * TPN + t];
        uint2 v2 = Hq[(long long)n2 * TPN + t];
        uint2 v3 = Hq[(long long)n3 * TPN + t];
        float2 p;
        p = __half22float2(*(__half2*)&v0.x); a0 += p.x; a1 += p.y;
        p = __half22float2(*(__half2*)&v0.y); a2 += p.x; a3 += p.y;
        p = __half22float2(*(__half2*)&v1.x); a0 += p.x; a1 += p.y;
        p = __half22float2(*(__half2*)&v1.y); a2 += p.x; a3 += p.y;
        p = __half22float2(*(__half2*)&v2.x); a0 += p.x; a1 += p.y;
        p = __half22float2(*(__half2*)&v2.y); a2 += p.x; a3 += p.y;
        p = __half22float2(*(__half2*)&v3.x); a0 += p.x; a1 += p.y;
        p = __half22float2(*(__half2*)&v3.y); a2 += p.x; a3 += p.y;
    }
    for (; e < end; e++) {
        int s = g_src_sorted[e];
        uint2 v = Hq[(long long)s * TPN + t];
        float2 p;
        p = __half22float2(*(__half2*)&v.x); a0 += p.x; a1 += p.y;
        p = __half22float2(*(__half2*)&v.y); a2 += p.x; a3 += p.y;
    }

    const float4 bv = *(const float4*)&bias[t * 4];
    float4 out;
    out.x = a0 * di + bv.x;
    out.y = a1 * di + bv.y;
    out.z = a2 * di + bv.z;
    out.w = a3 * di + bv.w;
    if (RELU) {
        out.x = fmaxf(out.x, 0.f); out.y = fmaxf(out.y, 0.f);
        out.z = fmaxf(out.z, 0.f); out.w = fmaxf(out.w, 0.f);
    }
    *(float4*)&Z[(long long)node * D + t * 4] = out;
}

// ---------------- decode: y[e] = dot(z2[a], z2[b]) (eli conversion inlined) ----------------
__global__ void decode_kernel(const void* __restrict__ eli_raw,
                              const float* __restrict__ Z,
                              float* __restrict__ y, int EL)
{
    int gw   = (blockIdx.x * blockDim.x + threadIdx.x) >> 5;
    int lane = threadIdx.x & 31;
    if (gw >= EL) return;
    int a, b;
    if (g_is64) {
        const long long* p = (const long long*)eli_raw;
        a = (int)p[gw]; b = (int)p[EL + gw];
    } else {
        const int* p = (const int*)eli_raw;
        a = p[gw]; b = p[EL + gw];
    }
    float4 za = *(const float4*)&Z[(long long)a * 128 + lane * 4];
    float4 zb = *(const float4*)&Z[(long long)b * 128 + lane * 4];
    float s = za.x * zb.x + za.y * zb.y + za.z * zb.z + za.w * zb.w;
    #pragma unroll
    for (int o = 16; o; o >>= 1) s += __shfl_down_sync(0xffffffffu, s, o);
    if (lane == 0) y[gw] = s;
}

// ---------------- launch ----------------
extern "C" void kernel_launch(void* const* d_in, const int* in_sizes, int n_in,
                              void* d_out, int out_size)
{
    const float* x   = (const float*)d_in[0];
    const void*  ei  = d_in[1];
    const void*  eli = d_in[2];
    const float* W1  = (const float*)d_in[3];
    const float* b1  = (const float*)d_in[4];
    const float* W2  = (const float*)d_in[5];
    const float* b2  = (const float*)d_in[6];
    float*       y   = (float*)d_out;

    const int E  = in_sizes[1] / 2;
    const int EL = in_sizes[2] / 2;

    __half *hh1p, *hh2p;
    float  *z1p, *z2p, *disp;
    cudaGetSymbolAddress((void**)&hh1p, g_hh1);
    cudaGetSymbolAddress((void**)&z1p,  g_z1);
    cudaGetSymbolAddress((void**)&hh2p, g_hh2);
    cudaGetSymbolAddress((void**)&z2p,  g_z2);
    cudaGetSymbolAddress((void**)&disp, g_dis);

    const int TB = 256;
    // --- prep ---
    zero_counts_kernel<<<(N_NODES + TB - 1) / TB, TB>>>();
    detect_kernel<<<1, 32>>>((const int*)ei);
    convert_edges_kernel<<<(E + TB - 1) / TB, TB>>>(ei, E);   // + degree count
    dis_kernel<<<(N_NODES + TB - 1) / TB, TB>>>();
    scan_kernel<<<1, 1024>>>(N_NODES);                         // + cursor copy
    fill_kernel<<<(E + TB - 1) / TB, TB>>>(E);

    // --- layer 1: hh1 = half(dis * (x@W1)); z1 = relu(agg + b1) ---
    {
        dim3 grid(D_H / 128, (N_NODES + 127) / 128);
        mma_gemm_kernel<<<grid, 256>>>(x, W1, hh1p, disp, N_NODES, D_H, D_IN);
    }
    agg_half_kernel<D_H, true><<<(N_NODES + 3) / 4, 256>>>(hh1p, z1p, b1);

    // --- layer 2: hh2 = half(dis * (z1@W2)); z2 = agg + b2 ---
    {
        dim3 grid(D_OUT / 128, (N_NODES + 127) / 128);
        mma_gemm_kernel<<<grid, 256>>>(z1p, W2, hh2p, disp, N_NODES, D_OUT, D_H);
    }
    agg_half_kernel<D_OUT, false><<<(N_NODES + 7) / 8, 256>>>(hh2p, z2p, b2);

    // --- decode ---
    decode_kernel<<<(EL * 32 + TB - 1) / TB, TB>>>(eli, z2p, y, EL);
}

// round 6
// speedup vs baseline: 2.1962x; 1.0566x over previous
#include <cuda_runtime.h>
#include <cuda_fp16.h>

#define N_NODES 50000
#define D_IN    256
#define D_H     256
#define D_OUT   128
#define MAX_E   1600000
#define MAX_EL  100000

// ---------------- scratch (device globals; no allocation) ----------------
__device__ int    g_is64;
__device__ int    g_src[MAX_E];
__device__ int    g_dst[MAX_E];
__device__ int    g_counts[N_NODES];
__device__ int    g_offsets[N_NODES + 1];
__device__ int    g_cursor[N_NODES];
__device__ float  g_dis[N_NODES];
__device__ int    g_src_sorted[MAX_E];
__device__ __half g_w1t[D_H * D_IN];       // W1^T [n][k] half
__device__ __half g_w2t[D_OUT * D_H];      // W2^T [n][k] half
__device__ __half g_hh1[N_NODES * D_H];    // half(dis[i] * (x@W1)[i])
__device__ __half g_z1h[N_NODES * D_H];    // relu(agg + b1) in half (GEMM2 A operand)
__device__ __half g_hh2[N_NODES * D_OUT];  // half(dis[i] * (z1@W2)[i])
__device__ float  g_z2[N_NODES * D_OUT];   // agg + b2 (fp32, decode operand)

// ---------------- weight convert + transpose (once per launch, ~5us) ----------------
__global__ void wconv_kernel(const float* __restrict__ W1,
                             const float* __restrict__ W2) {
    int i = blockIdx.x * blockDim.x + threadIdx.x;
    if (i < D_IN * D_H) {
        int k = i >> 8, n = i & 255;                 // W1[k][n]
        g_w1t[n * D_IN + k] = __float2half(W1[i]);
    }
    if (i < D_H * D_OUT) {
        int k = i >> 7, n = i & 127;                 // W2[k][n]
        g_w2t[n * D_H + k] = __float2half(W2[i]);
    }
}

// ---------------- init: zero counts + parallel dtype detect ----------------
__global__ void init_kernel(const int* __restrict__ raw) {
    int i = blockIdx.x * blockDim.x + threadIdx.x;
    if (i < N_NODES) g_counts[i] = 0;
    if (blockIdx.x == 0 && threadIdx.x < 32) {
        int nz = 0;
        for (int j = threadIdx.x; j < 256; j += 32)
            nz |= (raw[2 * j + 1] != 0);
        unsigned m = __ballot_sync(0xffffffffu, nz);
        if (threadIdx.x == 0) g_is64 = (m == 0);
    }
}

// convert + degree count fused
__global__ void convert_edges_kernel(const void* __restrict__ raw, int E) {
    int i = blockIdx.x * blockDim.x + threadIdx.x;
    if (i >= E) return;
    int s, d;
    if (g_is64) {
        const long long* p = (const long long*)raw;
        s = (int)p[i]; d = (int)p[E + i];
    } else {
        const int* p = (const int*)raw;
        s = p[i]; d = p[E + i];
    }
    g_src[i] = s;
    g_dst[i] = d;
    atomicAdd(&g_counts[d], 1);
}

// exclusive scan of counts -> offsets, + cursor copy, + dis = rsqrt(deg+1)
__global__ void scan_kernel(int n) {
    __shared__ int tmp[1024];
    __shared__ int carry;
    if (threadIdx.x == 0) carry = 0;
    __syncthreads();
    for (int base = 0; base < n; base += 1024) {
        int i = base + threadIdx.x;
        int v = (i < n) ? g_counts[i] : 0;
        tmp[threadIdx.x] = v;
        __syncthreads();
        for (int off = 1; off < 1024; off <<= 1) {
            int t = (threadIdx.x >= off) ? tmp[threadIdx.x - off] : 0;
            __syncthreads();
            tmp[threadIdx.x] += t;
            __syncthreads();
        }
        if (i < n) {
            int excl = carry + tmp[threadIdx.x] - v;
            g_offsets[i] = excl;
            g_cursor[i]  = excl;
            g_dis[i]     = rsqrtf((float)(v + 1));
        }
        __syncthreads();
        if (threadIdx.x == 1023) carry += tmp[1023];
        __syncthreads();
    }
    if (threadIdx.x == 0) g_offsets[n] = carry;
}

__global__ void fill_kernel(int E) {
    int i = blockIdx.x * blockDim.x + threadIdx.x;
    if (i < E) {
        int p = atomicAdd(&g_cursor[g_dst[i]], 1);
        g_src_sorted[p] = g_src[i];
    }
}

// ---------------- fp16 tensor-core GEMM: Ch = half(dis[m] * (A @ Wt^T)) ----------------
// A: [M,K] (fp32 or half), Bt: [N,K] half (transposed weights).
// Block 128x128, BK=32, 256 threads, 8 warps (4x2), warp tile 32x64.
// mma.sync.aligned.m16n8k16.row.col.f32.f16.f16.f32
#define LDH 40   // padded row length in halves: bank = (20*row + word) % 32, conflict-free

template<bool A_HALF>
__global__ __launch_bounds__(256) void hgemm_kernel(
    const void* __restrict__ Ain, const __half* __restrict__ Bt,
    __half* __restrict__ Ch, const float* __restrict__ dis,
    int M, int N, int K)
{
    __shared__ __half As[128][LDH];   // [m][k]
    __shared__ __half Bs[128][LDH];   // [n][k]

    const int tid  = threadIdx.x;
    const int lane = tid & 31;
    const int w    = tid >> 5;
    const int wm   = (w & 3) * 32;
    const int wn   = (w >> 2) * 64;
    const int bm   = blockIdx.y * 128;
    const int bn   = blockIdx.x * 128;
    const int r    = lane >> 2;
    const int c    = lane & 3;

    float acc[2][8][4];
    #pragma unroll
    for (int i = 0; i < 2; i++)
        #pragma unroll
        for (int j = 0; j < 8; j++)
            #pragma unroll
            for (int q = 0; q < 4; q++) acc[i][j][q] = 0.f;

    // staging: 256 threads; rows tid&127, half-of-tile tid>>7 (16 halves each)
    const int sr = tid & 127;
    const int sq = tid >> 7;            // 0/1 -> k-offset sq*16
    const int amg = bm + sr;
    const bool arow_ok = (amg < M);

    const float* Af = (const float*)Ain;
    const __half* Ah = (const __half*)Ain;

    float4 fa[4];      // fp32 A staging (16 floats)
    uint4  ha[2];      // half A staging (16 halves)
    uint4  hb[2];      // half B staging (16 halves)

    const int ntiles = K / 32;

    // prologue: stage tile 0
    {
        int k0 = sq * 16;
        if (A_HALF) {
            if (arow_ok) {
                ha[0] = *(const uint4*)&Ah[(long long)amg * K + k0];
                ha[1] = *(const uint4*)&Ah[(long long)amg * K + k0 + 8];
            } else { ha[0] = make_uint4(0,0,0,0); ha[1] = make_uint4(0,0,0,0); }
        } else {
            #pragma unroll
            for (int i = 0; i < 4; i++)
                fa[i] = arow_ok ? *(const float4*)&Af[(long long)amg * K + k0 + i * 4]
                                : make_float4(0.f,0.f,0.f,0.f);
        }
        hb[0] = *(const uint4*)&Bt[(long long)(bn + sr) * K + k0];
        hb[1] = *(const uint4*)&Bt[(long long)(bn + sr) * K + k0 + 8];
    }

    for (int kt = 0; kt < ntiles; kt++) {
        __syncthreads();
        // commit staged tile to smem
        if (A_HALF) {
            *(uint4*)&As[sr][sq * 16]     = ha[0];
            *(uint4*)&As[sr][sq * 16 + 8] = ha[1];
        } else {
            __half2 h8[8];
            h8[0] = __floats2half2_rn(fa[0].x, fa[0].y);
            h8[1] = __floats2half2_rn(fa[0].z, fa[0].w);
            h8[2] = __floats2half2_rn(fa[1].x, fa[1].y);
            h8[3] = __floats2half2_rn(fa[1].z, fa[1].w);
            h8[4] = __floats2half2_rn(fa[2].x, fa[2].y);
            h8[5] = __floats2half2_rn(fa[2].z, fa[2].w);
            h8[6] = __floats2half2_rn(fa[3].x, fa[3].y);
            h8[7] = __floats2half2_rn(fa[3].z, fa[3].w);
            *(uint4*)&As[sr][sq * 16]     = *(uint4*)&h8[0];
            *(uint4*)&As[sr][sq * 16 + 8] = *(uint4*)&h8[4];
        }
        *(uint4*)&Bs[sr][sq * 16]     = hb[0];
        *(uint4*)&Bs[sr][sq * 16 + 8] = hb[1];
        __syncthreads();

        // prefetch next tile
        if (kt + 1 < ntiles) {
            int k0 = (kt + 1) * 32 + sq * 16;
            if (A_HALF) {
                if (arow_ok) {
                    ha[0] = *(const uint4*)&Ah[(long long)amg * K + k0];
                    ha[1] = *(const uint4*)&Ah[(long long)amg * K + k0 + 8];
                }
            } else {
                #pragma unroll
                for (int i = 0; i < 4; i++)
                    fa[i] = arow_ok ? *(const float4*)&Af[(long long)amg * K + k0 + i * 4]
                                    : make_float4(0.f,0.f,0.f,0.f);
            }
            hb[0] = *(const uint4*)&Bt[(long long)(bn + sr) * K + k0];
            hb[1] = *(const uint4*)&Bt[(long long)(bn + sr) * K + k0 + 8];
        }

        // compute: 2 k16 steps
        #pragma unroll
        for (int ks = 0; ks < 2; ks++) {
            int kk = ks * 16;
            unsigned af[2][4];
            #pragma unroll
            for (int tm = 0; tm < 2; tm++) {
                int mb = wm + tm * 16;
                af[tm][0] = *(const unsigned*)&As[mb + r    ][kk + c * 2    ];
                af[tm][1] = *(const unsigned*)&As[mb + r + 8][kk + c * 2    ];
                af[tm][2] = *(const unsigned*)&As[mb + r    ][kk + c * 2 + 8];
                af[tm][3] = *(const unsigned*)&As[mb + r + 8][kk + c * 2 + 8];
            }
            unsigned bf[8][2];
            #pragma unroll
            for (int tn = 0; tn < 8; tn++) {
                int nb = wn + tn * 8 + r;
                bf[tn][0] = *(const unsigned*)&Bs[nb][kk + c * 2    ];
                bf[tn][1] = *(const unsigned*)&Bs[nb][kk + c * 2 + 8];
            }
            #pragma unroll
            for (int tm = 0; tm < 2; tm++)
                #pragma unroll
                for (int tn = 0; tn < 8; tn++) {
                    asm volatile(
                        "mma.sync.aligned.m16n8k16.row.col.f32.f16.f16.f32 "
                        "{%0,%1,%2,%3}, {%4,%5,%6,%7}, {%8,%9}, {%0,%1,%2,%3};"
                        : "+f"(acc[tm][tn][0]), "+f"(acc[tm][tn][1]),
                          "+f"(acc[tm][tn][2]), "+f"(acc[tm][tn][3])
                        : "r"(af[tm][0]), "r"(af[tm][1]),
                          "r"(af[tm][2]), "r"(af[tm][3]),
                          "r"(bf[tn][0]), "r"(bf[tn][1]));
                }
        }
    }

    // fused epilogue: scale by dis[row], convert to half
    #pragma unroll
    for (int tm = 0; tm < 2; tm++) {
        int row0 = bm + wm + tm * 16 + r;
        int row1 = row0 + 8;
        float s0 = (row0 < M) ? dis[row0] : 0.f;
        float s1 = (row1 < M) ? dis[row1] : 0.f;
        #pragma unroll
        for (int tn = 0; tn < 8; tn++) {
            int col = bn + wn + tn * 8 + c * 2;
            if (row0 < M) {
                __half2 hv = __floats2half2_rn(acc[tm][tn][0] * s0,
                                               acc[tm][tn][1] * s0);
                *(__half2*)&Ch[(long long)row0 * N + col] = hv;
            }
            if (row1 < M) {
                __half2 hv = __floats2half2_rn(acc[tm][tn][2] * s1,
                                               acc[tm][tn][3] * s1);
                *(__half2*)&Ch[(long long)row1 * N + col] = hv;
            }
        }
    }
}

// ---------------- aggregation (half gathers, pre-scaled) ----------------
// z[i] = f( di * ( hh[i] + sum_{s in N(i)} hh[s] ) + b )   where hh = h*dis
template<int D, bool RELU, bool OUT_HALF>
__global__ __launch_bounds__(256) void agg_half_kernel(
    const __half* __restrict__ HH, void* __restrict__ Zout,
    const float* __restrict__ bias)
{
    constexpr int TPN = D / 4;          // threads per node (half4 each)
    constexpr int NPB = 256 / TPN;      // nodes per block
    const int node = blockIdx.x * NPB + threadIdx.x / TPN;
    const int t    = threadIdx.x % TPN;
    if (node >= N_NODES) return;

    const float di = g_dis[node];
    const uint2* Hq = (const uint2*)HH;

    // self loop contributes hh[node] (outer *di makes it h*di^2)
    uint2 sv = Hq[(long long)node * TPN + t];
    float2 s0 = __half22float2(*(__half2*)&sv.x);
    float2 s1 = __half22float2(*(__half2*)&sv.y);
    float a0 = s0.x, a1 = s0.y, a2 = s1.x, a3 = s1.y;

    int e   = g_offsets[node];
    int end = g_offsets[node + 1];

    for (; e + 4 <= end; e += 4) {
        int n0 = g_src_sorted[e + 0];
        int n1 = g_src_sorted[e + 1];
        int n2 = g_src_sorted[e + 2];
        int n3 = g_src_sorted[e + 3];
        uint2 v0 = Hq[(long long)n0 * TPN + t];
        uint2 v1 = Hq[(long long)n1 * TPN + t];
        uint2 v2 = Hq[(long long)n2 * TPN + t];
        uint2 v3 = Hq[(long long)n3 * TPN + t];
        float2 p;
        p = __half22float2(*(__half2*)&v0.x); a0 += p.x; a1 += p.y;
        p = __half22float2(*(__half2*)&v0.y); a2 += p.x; a3 += p.y;
        p = __half22float2(*(__half2*)&v1.x); a0 += p.x; a1 += p.y;
        p = __half22float2(*(__half2*)&v1.y); a2 += p.x; a3 += p.y;
        p = __half22float2(*(__half2*)&v2.x); a0 += p.x; a1 += p.y;
        p = __half22float2(*(__half2*)&v2.y); a2 += p.x; a3 += p.y;
        p = __half22float2(*(__half2*)&v3.x); a0 += p.x; a1 += p.y;
        p = __half22float2(*(__half2*)&v3.y); a2 += p.x; a3 += p.y;
    }
    for (; e < end; e++) {
        int s = g_src_sorted[e];
        uint2 v = Hq[(long long)s * TPN + t];
        float2 p;
        p = __half22float2(*(__half2*)&v.x); a0 += p.x; a1 += p.y;
        p = __half22float2(*(__half2*)&v.y); a2 += p.x; a3 += p.y;
    }

    const float4 bv = *(const float4*)&bias[t * 4];
    float o0 = a0 * di + bv.x;
    float o1 = a1 * di + bv.y;
    float o2 = a2 * di + bv.z;
    float o3 = a3 * di + bv.w;
    if (RELU) {
        o0 = fmaxf(o0, 0.f); o1 = fmaxf(o1, 0.f);
        o2 = fmaxf(o2, 0.f); o3 = fmaxf(o3, 0.f);
    }
    if (OUT_HALF) {
        __half2 h0 = __floats2half2_rn(o0, o1);
        __half2 h1 = __floats2half2_rn(o2, o3);
        uint2 st; st.x = *(unsigned*)&h0; st.y = *(unsigned*)&h1;
        *(uint2*)&((__half*)Zout)[(long long)node * D + t * 4] = st;
    } else {
        float4 out = make_float4(o0, o1, o2, o3);
        *(float4*)&((float*)Zout)[(long long)node * D + t * 4] = out;
    }
}

// ---------------- decode: y[e] = dot(z2[a], z2[b]) ----------------
__global__ void decode_kernel(const void* __restrict__ eli_raw,
                              const float* __restrict__ Z,
                              float* __restrict__ y, int EL)
{
    int gw   = (blockIdx.x * blockDim.x + threadIdx.x) >> 5;
    int lane = threadIdx.x & 31;
    if (gw >= EL) return;
    int a, b;
    if (g_is64) {
        const long long* p = (const long long*)eli_raw;
        a = (int)p[gw]; b = (int)p[EL + gw];
    } else {
        const int* p = (const int*)eli_raw;
        a = p[gw]; b = p[EL + gw];
    }
    float4 za = *(const float4*)&Z[(long long)a * 128 + lane * 4];
    float4 zb = *(const float4*)&Z[(long long)b * 128 + lane * 4];
    float s = za.x * zb.x + za.y * zb.y + za.z * zb.z + za.w * zb.w;
    #pragma unroll
    for (int o = 16; o; o >>= 1) s += __shfl_down_sync(0xffffffffu, s, o);
    if (lane == 0) y[gw] = s;
}

// ---------------- launch ----------------
extern "C" void kernel_launch(void* const* d_in, const int* in_sizes, int n_in,
                              void* d_out, int out_size)
{
    const float* x   = (const float*)d_in[0];
    const void*  ei  = d_in[1];
    const void*  eli = d_in[2];
    const float* W1  = (const float*)d_in[3];
    const float* b1  = (const float*)d_in[4];
    const float* W2  = (const float*)d_in[5];
    const float* b2  = (const float*)d_in[6];
    float*       y   = (float*)d_out;

    const int E  = in_sizes[1] / 2;
    const int EL = in_sizes[2] / 2;

    __half *hh1p, *z1hp, *hh2p, *w1tp, *w2tp;
    float  *z2p, *disp;
    cudaGetSymbolAddress((void**)&hh1p, g_hh1);
    cudaGetSymbolAddress((void**)&z1hp, g_z1h);
    cudaGetSymbolAddress((void**)&hh2p, g_hh2);
    cudaGetSymbolAddress((void**)&z2p,  g_z2);
    cudaGetSymbolAddress((void**)&disp, g_dis);
    cudaGetSymbolAddress((void**)&w1tp, g_w1t);
    cudaGetSymbolAddress((void**)&w2tp, g_w2t);

    const int TB = 256;
    // 1. weight convert+transpose
    wconv_kernel<<<(D_IN * D_H + TB - 1) / TB, TB>>>(W1, W2);
    // 2. zero counts + dtype detect
    init_kernel<<<(N_NODES + TB - 1) / TB, TB>>>((const int*)ei);
    // 3. edge convert + degree count
    convert_edges_kernel<<<(E + TB - 1) / TB, TB>>>(ei, E);
    // 4. scan (+cursor, +dis)
    scan_kernel<<<1, 1024>>>(N_NODES);
    // 5. CSR fill
    fill_kernel<<<(E + TB - 1) / TB, TB>>>(E);

    // 6. layer 1 GEMM: hh1 = half(dis * (x@W1))
    {
        dim3 grid(D_H / 128, (N_NODES + 127) / 128);
        hgemm_kernel<false><<<grid, 256>>>(x, w1tp, hh1p, disp, N_NODES, D_H, D_IN);
    }
    // 7. layer 1 aggregation -> z1 (half)
    agg_half_kernel<D_H, true, true><<<(N_NODES + 3) / 4, 256>>>(hh1p, z1hp, b1);

    // 8. layer 2 GEMM: hh2 = half(dis * (z1@W2))
    {
        dim3 grid(D_OUT / 128, (N_NODES + 127) / 128);
        hgemm_kernel<true><<<grid, 256>>>(z1hp, w2tp, hh2p, disp, N_NODES, D_OUT, D_H);
    }
    // 9. layer 2 aggregation -> z2 (fp32)
    agg_half_kernel<D_OUT, false, false><<<(N_NODES + 7) / 8, 256>>>(hh2p, z2p, b2);

    // 10. decode
    decode_kernel<<<(EL * 32 + TB - 1) / TB, TB>>>(eli, z2p, y, EL);
}

// round 7
// speedup vs baseline: 2.7922x; 1.2714x over previous
#include <cuda_runtime.h>
#include <cuda_fp16.h>

#define N_NODES 50000
#define D_IN    256
#define D_H     256
#define D_OUT   128
#define MAX_E   1600000
#define MAX_EL  100000
#define SCAN_B  49          // ceil(50000/1024)

// ---------------- scratch (device globals; no allocation) ----------------
__device__ int    g_is64;
__device__ int    g_src[MAX_E];
__device__ int    g_dst[MAX_E];
__device__ int    g_counts[N_NODES];
__device__ int    g_offsets[N_NODES + 1];
__device__ int    g_cursor[N_NODES];
__device__ int    g_bsums[64];
__device__ float  g_dis[N_NODES];
__device__ int    g_src_sorted[MAX_E];
__device__ __half g_w1t[D_H * D_IN];       // W1^T [n][k] half
__device__ __half g_w2t[D_OUT * D_H];      // W2^T [n][k] half
__device__ __half g_hh1[N_NODES * D_H];    // half(dis[i] * (x@W1)[i])
__device__ __half g_z1h[N_NODES * D_H];    // relu(agg + b1) half (GEMM2 A)
__device__ __half g_hh2[N_NODES * D_OUT];  // half(dis[i] * (z1@W2)[i])
__device__ float  g_z2[N_NODES * D_OUT];   // agg + b2 (fp32, decode operand)

// ---------------- weight convert + transpose ----------------
__global__ void wconv_kernel(const float* __restrict__ W1,
                             const float* __restrict__ W2) {
    int i = blockIdx.x * blockDim.x + threadIdx.x;
    if (i < D_IN * D_H) {
        int k = i >> 8, n = i & 255;                 // W1[k][n]
        g_w1t[n * D_IN + k] = __float2half(W1[i]);
    }
    if (i < D_H * D_OUT) {
        int k = i >> 7, n = i & 127;                 // W2[k][n]
        g_w2t[n * D_H + k] = __float2half(W2[i]);
    }
}

// ---------------- init: zero counts + parallel dtype detect ----------------
__global__ void init_kernel(const int* __restrict__ raw) {
    int i = blockIdx.x * blockDim.x + threadIdx.x;
    if (i < N_NODES) g_counts[i] = 0;
    if (blockIdx.x == 0 && threadIdx.x < 32) {
        int nz = 0;
        for (int j = threadIdx.x; j < 256; j += 32)
            nz |= (raw[2 * j + 1] != 0);
        unsigned m = __ballot_sync(0xffffffffu, nz);
        if (threadIdx.x == 0) g_is64 = (m == 0);
    }
}

// convert + degree count fused
__global__ void convert_edges_kernel(const void* __restrict__ raw, int E) {
    int i = blockIdx.x * blockDim.x + threadIdx.x;
    if (i >= E) return;
    int s, d;
    if (g_is64) {
        const long long* p = (const long long*)raw;
        s = (int)p[i]; d = (int)p[E + i];
    } else {
        const int* p = (const int*)raw;
        s = p[i]; d = p[E + i];
    }
    g_src[i] = s;
    g_dst[i] = d;
    atomicAdd(&g_counts[d], 1);
}

// ---------------- 3-phase parallel exclusive scan ----------------
// phase 1: block-local exclusive scan (warp shuffles), block sums, dis
__global__ __launch_bounds__(1024) void scan_part1(int n) {
    int i = blockIdx.x * 1024 + threadIdx.x;
    int v = (i < n) ? g_counts[i] : 0;
    int lane = threadIdx.x & 31, wid = threadIdx.x >> 5;

    int x = v;
    #pragma unroll
    for (int o = 1; o < 32; o <<= 1) {
        int t = __shfl_up_sync(0xffffffffu, x, o);
        if (lane >= o) x += t;
    }
    __shared__ int wsum[32];
    if (lane == 31) wsum[wid] = x;
    __syncthreads();
    if (wid == 0) {
        int ws = wsum[lane];
        #pragma unroll
        for (int o = 1; o < 32; o <<= 1) {
            int t = __shfl_up_sync(0xffffffffu, ws, o);
            if (lane >= o) ws += t;
        }
        wsum[lane] = ws;
    }
    __syncthreads();
    int incl = x + (wid > 0 ? wsum[wid - 1] : 0);
    if (i < n) {
        g_offsets[i] = incl - v;                    // local exclusive
        g_dis[i] = rsqrtf((float)(v + 1));          // deg incl self-loop
    }
    if (threadIdx.x == 1023) g_bsums[blockIdx.x] = incl;
}

// phase 2: scan the SCAN_B block sums (1 block, 64 threads)
__global__ void scan_part2(int nb, int n) {
    __shared__ int ws[2];
    int lane = threadIdx.x & 31, w = threadIdx.x >> 5;
    int v = (threadIdx.x < nb) ? g_bsums[threadIdx.x] : 0;
    int x = v;
    #pragma unroll
    for (int o = 1; o < 32; o <<= 1) {
        int t = __shfl_up_sync(0xffffffffu, x, o);
        if (lane >= o) x += t;
    }
    if (lane == 31) ws[w] = x;
    __syncthreads();
    int incl = x + ((w == 1) ? ws[0] : 0);
    if (threadIdx.x < nb) g_bsums[threadIdx.x] = incl - v;   // exclusive
    if (threadIdx.x == nb - 1) g_offsets[n] = incl;          // total = E
}

// phase 3: add block base; write final offsets + cursor
__global__ __launch_bounds__(1024) void scan_part3(int n) {
    int i = blockIdx.x * 1024 + threadIdx.x;
    if (i < n) {
        int off = g_offsets[i] + g_bsums[blockIdx.x];
        g_offsets[i] = off;
        g_cursor[i]  = off;
    }
}

__global__ void fill_kernel(int E) {
    int i = blockIdx.x * blockDim.x + threadIdx.x;
    if (i < E) {
        int p = atomicAdd(&g_cursor[g_dst[i]], 1);
        g_src_sorted[p] = g_src[i];
    }
}

// ---------------- fp16 tensor-core GEMM: Ch = half(dis[m] * (A @ Bt^T)) ----------------
#define LDH 40   // padded row (halves): bank = (20*row + word) % 32, conflict-free

template<bool A_HALF>
__global__ __launch_bounds__(256) void hgemm_kernel(
    const void* __restrict__ Ain, const __half* __restrict__ Bt,
    __half* __restrict__ Ch, const float* __restrict__ dis,
    int M, int N, int K)
{
    __shared__ __half As[128][LDH];   // [m][k]
    __shared__ __half Bs[128][LDH];   // [n][k]

    const int tid  = threadIdx.x;
    const int lane = tid & 31;
    const int w    = tid >> 5;
    const int wm   = (w & 3) * 32;
    const int wn   = (w >> 2) * 64;
    const int bm   = blockIdx.y * 128;
    const int bn   = blockIdx.x * 128;
    const int r    = lane >> 2;
    const int c    = lane & 3;

    float acc[2][8][4];
    #pragma unroll
    for (int i = 0; i < 2; i++)
        #pragma unroll
        for (int j = 0; j < 8; j++)
            #pragma unroll
            for (int q = 0; q < 4; q++) acc[i][j][q] = 0.f;

    const int sr = tid & 127;
    const int sq = tid >> 7;            // 0/1 -> k-offset sq*16
    const int amg = bm + sr;
    const bool arow_ok = (amg < M);

    const float* Af = (const float*)Ain;
    const __half* Ah = (const __half*)Ain;

    float4 fa[4];
    uint4  ha[2];
    uint4  hb[2];

    const int ntiles = K / 32;

    {
        int k0 = sq * 16;
        if (A_HALF) {
            if (arow_ok) {
                ha[0] = *(const uint4*)&Ah[(long long)amg * K + k0];
                ha[1] = *(const uint4*)&Ah[(long long)amg * K + k0 + 8];
            } else { ha[0] = make_uint4(0,0,0,0); ha[1] = make_uint4(0,0,0,0); }
        } else {
            #pragma unroll
            for (int i = 0; i < 4; i++)
                fa[i] = arow_ok ? *(const float4*)&Af[(long long)amg * K + k0 + i * 4]
                                : make_float4(0.f,0.f,0.f,0.f);
        }
        hb[0] = *(const uint4*)&Bt[(long long)(bn + sr) * K + k0];
        hb[1] = *(const uint4*)&Bt[(long long)(bn + sr) * K + k0 + 8];
    }

    for (int kt = 0; kt < ntiles; kt++) {
        __syncthreads();
        if (A_HALF) {
            *(uint4*)&As[sr][sq * 16]     = ha[0];
            *(uint4*)&As[sr][sq * 16 + 8] = ha[1];
        } else {
            __half2 h8[8];
            h8[0] = __floats2half2_rn(fa[0].x, fa[0].y);
            h8[1] = __floats2half2_rn(fa[0].z, fa[0].w);
            h8[2] = __floats2half2_rn(fa[1].x, fa[1].y);
            h8[3] = __floats2half2_rn(fa[1].z, fa[1].w);
            h8[4] = __floats2half2_rn(fa[2].x, fa[2].y);
            h8[5] = __floats2half2_rn(fa[2].z, fa[2].w);
            h8[6] = __floats2half2_rn(fa[3].x, fa[3].y);
            h8[7] = __floats2half2_rn(fa[3].z, fa[3].w);
            *(uint4*)&As[sr][sq * 16]     = *(uint4*)&h8[0];
            *(uint4*)&As[sr][sq * 16 + 8] = *(uint4*)&h8[4];
        }
        *(uint4*)&Bs[sr][sq * 16]     = hb[0];
        *(uint4*)&Bs[sr][sq * 16 + 8] = hb[1];
        __syncthreads();

        if (kt + 1 < ntiles) {
            int k0 = (kt + 1) * 32 + sq * 16;
            if (A_HALF) {
                if (arow_ok) {
                    ha[0] = *(const uint4*)&Ah[(long long)amg * K + k0];
                    ha[1] = *(const uint4*)&Ah[(long long)amg * K + k0 + 8];
                }
            } else {
                #pragma unroll
                for (int i = 0; i < 4; i++)
                    fa[i] = arow_ok ? *(const float4*)&Af[(long long)amg * K + k0 + i * 4]
                                    : make_float4(0.f,0.f,0.f,0.f);
            }
            hb[0] = *(const uint4*)&Bt[(long long)(bn + sr) * K + k0];
            hb[1] = *(const uint4*)&Bt[(long long)(bn + sr) * K + k0 + 8];
        }

        #pragma unroll
        for (int ks = 0; ks < 2; ks++) {
            int kk = ks * 16;
            unsigned af[2][4];
            #pragma unroll
            for (int tm = 0; tm < 2; tm++) {
                int mb = wm + tm * 16;
                af[tm][0] = *(const unsigned*)&As[mb + r    ][kk + c * 2    ];
                af[tm][1] = *(const unsigned*)&As[mb + r + 8][kk + c * 2    ];
                af[tm][2] = *(const unsigned*)&As[mb + r    ][kk + c * 2 + 8];
                af[tm][3] = *(const unsigned*)&As[mb + r + 8][kk + c * 2 + 8];
            }
            unsigned bf[8][2];
            #pragma unroll
            for (int tn = 0; tn < 8; tn++) {
                int nb = wn + tn * 8 + r;
                bf[tn][0] = *(const unsigned*)&Bs[nb][kk + c * 2    ];
                bf[tn][1] = *(const unsigned*)&Bs[nb][kk + c * 2 + 8];
            }
            #pragma unroll
            for (int tm = 0; tm < 2; tm++)
                #pragma unroll
                for (int tn = 0; tn < 8; tn++) {
                    asm volatile(
                        "mma.sync.aligned.m16n8k16.row.col.f32.f16.f16.f32 "
                        "{%0,%1,%2,%3}, {%4,%5,%6,%7}, {%8,%9}, {%0,%1,%2,%3};"
                        : "+f"(acc[tm][tn][0]), "+f"(acc[tm][tn][1]),
                          "+f"(acc[tm][tn][2]), "+f"(acc[tm][tn][3])
                        : "r"(af[tm][0]), "r"(af[tm][1]),
                          "r"(af[tm][2]), "r"(af[tm][3]),
                          "r"(bf[tn][0]), "r"(bf[tn][1]));
                }
        }
    }

    #pragma unroll
    for (int tm = 0; tm < 2; tm++) {
        int row0 = bm + wm + tm * 16 + r;
        int row1 = row0 + 8;
        float s0 = (row0 < M) ? dis[row0] : 0.f;
        float s1 = (row1 < M) ? dis[row1] : 0.f;
        #pragma unroll
        for (int tn = 0; tn < 8; tn++) {
            int col = bn + wn + tn * 8 + c * 2;
            if (row0 < M) {
                __half2 hv = __floats2half2_rn(acc[tm][tn][0] * s0,
                                               acc[tm][tn][1] * s0);
                *(__half2*)&Ch[(long long)row0 * N + col] = hv;
            }
            if (row1 < M) {
                __half2 hv = __floats2half2_rn(acc[tm][tn][2] * s1,
                                               acc[tm][tn][3] * s1);
                *(__half2*)&Ch[(long long)row1 * N + col] = hv;
            }
        }
    }
}

// ---------------- aggregation (half gathers, pre-scaled) ----------------
// z[i] = f( di * ( hh[i] + sum_{s in N(i)} hh[s] ) + b )   where hh = h*dis
template<int D, bool RELU, bool OUT_HALF>
__global__ __launch_bounds__(256) void agg_half_kernel(
    const __half* __restrict__ HH, void* __restrict__ Zout,
    const float* __restrict__ bias)
{
    constexpr int TPN = D / 4;
    constexpr int NPB = 256 / TPN;
    const int node = blockIdx.x * NPB + threadIdx.x / TPN;
    const int t    = threadIdx.x % TPN;
    if (node >= N_NODES) return;

    const float di = g_dis[node];
    const uint2* Hq = (const uint2*)HH;

    uint2 sv = Hq[(long long)node * TPN + t];
    float2 s0 = __half22float2(*(__half2*)&sv.x);
    float2 s1 = __half22float2(*(__half2*)&sv.y);
    float a0 = s0.x, a1 = s0.y, a2 = s1.x, a3 = s1.y;

    int e   = g_offsets[node];
    int end = g_offsets[node + 1];

    for (; e + 4 <= end; e += 4) {
        int n0 = g_src_sorted[e + 0];
        int n1 = g_src_sorted[e + 1];
        int n2 = g_src_sorted[e + 2];
        int n3 = g_src_sorted[e + 3];
        uint2 v0 = Hq[(long long)n0 * TPN + t];
        uint2 v1 = Hq[(long long)n1 * TPN + t];
        uint2 v2 = Hq[(long long)n2 * TPN + t];
        uint2 v3 = Hq[(long long)n3 * TPN + t];
        float2 p;
        p = __half22float2(*(__half2*)&v0.x); a0 += p.x; a1 += p.y;
        p = __half22float2(*(__half2*)&v0.y); a2 += p.x; a3 += p.y;
        p = __half22float2(*(__half2*)&v1.x); a0 += p.x; a1 += p.y;
        p = __half22float2(*(__half2*)&v1.y); a2 += p.x; a3 += p.y;
        p = __half22float2(*(__half2*)&v2.x); a0 += p.x; a1 += p.y;
        p = __half22float2(*(__half2*)&v2.y); a2 += p.x; a3 += p.y;
        p = __half22float2(*(__half2*)&v3.x); a0 += p.x; a1 += p.y;
        p = __half22float2(*(__half2*)&v3.y); a2 += p.x; a3 += p.y;
    }
    for (; e < end; e++) {
        int s = g_src_sorted[e];
        uint2 v = Hq[(long long)s * TPN + t];
        float2 p;
        p = __half22float2(*(__half2*)&v.x); a0 += p.x; a1 += p.y;
        p = __half22float2(*(__half2*)&v.y); a2 += p.x; a3 += p.y;
    }

    const float4 bv = *(const float4*)&bias[t * 4];
    float o0 = a0 * di + bv.x;
    float o1 = a1 * di + bv.y;
    float o2 = a2 * di + bv.z;
    float o3 = a3 * di + bv.w;
    if (RELU) {
        o0 = fmaxf(o0, 0.f); o1 = fmaxf(o1, 0.f);
        o2 = fmaxf(o2, 0.f); o3 = fmaxf(o3, 0.f);
    }
    if (OUT_HALF) {
        __half2 h0 = __floats2half2_rn(o0, o1);
        __half2 h1 = __floats2half2_rn(o2, o3);
        uint2 st; st.x = *(unsigned*)&h0; st.y = *(unsigned*)&h1;
        *(uint2*)&((__half*)Zout)[(long long)node * D + t * 4] = st;
    } else {
        float4 out = make_float4(o0, o1, o2, o3);
        *(float4*)&((float*)Zout)[(long long)node * D + t * 4] = out;
    }
}

// ---------------- decode: y[e] = dot(z2[a], z2[b]) ----------------
__global__ void decode_kernel(const void* __restrict__ eli_raw,
                              const float* __restrict__ Z,
                              float* __restrict__ y, int EL)
{
    int gw   = (blockIdx.x * blockDim.x + threadIdx.x) >> 5;
    int lane = threadIdx.x & 31;
    if (gw >= EL) return;
    int a, b;
    if (g_is64) {
        const long long* p = (const long long*)eli_raw;
        a = (int)p[gw]; b = (int)p[EL + gw];
    } else {
        const int* p = (const int*)eli_raw;
        a = p[gw]; b = p[EL + gw];
    }
    float4 za = *(const float4*)&Z[(long long)a * 128 + lane * 4];
    float4 zb = *(const float4*)&Z[(long long)b * 128 + lane * 4];
    float s = za.x * zb.x + za.y * zb.y + za.z * zb.z + za.w * zb.w;
    #pragma unroll
    for (int o = 16; o; o >>= 1) s += __shfl_down_sync(0xffffffffu, s, o);
    if (lane == 0) y[gw] = s;
}

// ---------------- launch ----------------
extern "C" void kernel_launch(void* const* d_in, const int* in_sizes, int n_in,
                              void* d_out, int out_size)
{
    const float* x   = (const float*)d_in[0];
    const void*  ei  = d_in[1];
    const void*  eli = d_in[2];
    const float* W1  = (const float*)d_in[3];
    const float* b1  = (const float*)d_in[4];
    const float* W2  = (const float*)d_in[5];
    const float* b2  = (const float*)d_in[6];
    float*       y   = (float*)d_out;

    const int E  = in_sizes[1] / 2;
    const int EL = in_sizes[2] / 2;

    __half *hh1p, *z1hp, *hh2p, *w1tp, *w2tp;
    float  *z2p, *disp;
    cudaGetSymbolAddress((void**)&hh1p, g_hh1);
    cudaGetSymbolAddress((void**)&z1hp, g_z1h);
    cudaGetSymbolAddress((void**)&hh2p, g_hh2);
    cudaGetSymbolAddress((void**)&z2p,  g_z2);
    cudaGetSymbolAddress((void**)&disp, g_dis);
    cudaGetSymbolAddress((void**)&w1tp, g_w1t);
    cudaGetSymbolAddress((void**)&w2tp, g_w2t);

    const int TB = 256;
    wconv_kernel<<<(D_IN * D_H + TB - 1) / TB, TB>>>(W1, W2);
    init_kernel<<<(N_NODES + TB - 1) / TB, TB>>>((const int*)ei);
    convert_edges_kernel<<<(E + TB - 1) / TB, TB>>>(ei, E);
    scan_part1<<<SCAN_B, 1024>>>(N_NODES);
    scan_part2<<<1, 64>>>(SCAN_B, N_NODES);
    scan_part3<<<SCAN_B, 1024>>>(N_NODES);
    fill_kernel<<<(E + TB - 1) / TB, TB>>>(E);

    // layer 1
    {
        dim3 grid(D_H / 128, (N_NODES + 127) / 128);
        hgemm_kernel<false><<<grid, 256>>>(x, w1tp, hh1p, disp, N_NODES, D_H, D_IN);
    }
    agg_half_kernel<D_H, true, true><<<(N_NODES + 3) / 4, 256>>>(hh1p, z1hp, b1);

    // layer 2
    {
        dim3 grid(D_OUT / 128, (N_NODES + 127) / 128);
        hgemm_kernel<true><<<grid, 256>>>(z1hp, w2tp, hh2p, disp, N_NODES, D_OUT, D_H);
    }
    agg_half_kernel<D_OUT, false, false><<<(N_NODES + 7) / 8, 256>>>(hh2p, z2p, b2);

    // decode
    decode_kernel<<<(EL * 32 + TB - 1) / TB, TB>>>(eli, z2p, y, EL);
}

// round 8
// speedup vs baseline: 2.7963x; 1.0015x over previous
#include <cuda_runtime.h>
#include <cuda_fp16.h>

#define N_NODES 50000
#define D_IN    256
#define D_H     256
#define D_OUT   128
#define MAX_E   1600000
#define MAX_EL  100000
#define SCAN_B  49          // ceil(50000/1024)

// ---------------- scratch (device globals; no allocation) ----------------
__device__ int    g_is64;
__device__ int    g_counts[N_NODES];
__device__ int    g_offsets[N_NODES + 1];
__device__ int    g_cursor[N_NODES];
__device__ int    g_bsums[64];
__device__ float  g_dis[N_NODES];
__device__ int    g_src_sorted[MAX_E];
__device__ __half g_w1t[D_H * D_IN];       // W1^T [n][k] half
__device__ __half g_w2t[D_OUT * D_H];      // W2^T [n][k] half
__device__ __half g_hh1[N_NODES * D_H];    // half(dis[i] * (x@W1)[i])
__device__ __half g_z1h[N_NODES * D_H];    // relu(agg + b1) half (GEMM2 A)
__device__ __half g_hh2[N_NODES * D_OUT];  // half(dis[i] * (z1@W2)[i])
__device__ float  g_z2[N_NODES * D_OUT];   // agg + b2 (fp32, decode operand)

// ---------------- fused init: weight transpose+convert, zero counts, detect ----------------
__global__ void init_kernel(const float* __restrict__ W1,
                            const float* __restrict__ W2,
                            const int* __restrict__ raw) {
    int i = blockIdx.x * blockDim.x + threadIdx.x;
    if (i < D_IN * D_H) {
        int k = i >> 8, n = i & 255;                 // W1[k][n]
        g_w1t[n * D_IN + k] = __float2half(W1[i]);
    }
    if (i < D_H * D_OUT) {
        int k = i >> 7, n = i & 127;                 // W2[k][n]
        g_w2t[n * D_H + k] = __float2half(W2[i]);
    }
    if (i < N_NODES) g_counts[i] = 0;
    if (blockIdx.x == 0 && threadIdx.x < 32) {
        int nz = 0;
        for (int j = threadIdx.x; j < 256; j += 32)
            nz |= (raw[2 * j + 1] != 0);
        unsigned m = __ballot_sync(0xffffffffu, nz);
        if (threadIdx.x == 0) g_is64 = (m == 0);
    }
}

// degree count straight from raw dst row
__global__ void count_kernel(const void* __restrict__ raw, int E) {
    int i = blockIdx.x * blockDim.x + threadIdx.x;
    if (i >= E) return;
    int d;
    if (g_is64) d = (int)((const long long*)raw)[E + i];
    else        d = ((const int*)raw)[E + i];
    atomicAdd(&g_counts[d], 1);
}

__global__ void dis_kernel() {
    int i = blockIdx.x * blockDim.x + threadIdx.x;
    if (i < N_NODES) g_dis[i] = rsqrtf((float)(g_counts[i] + 1));
}

// ---------------- 3-phase parallel exclusive scan ----------------
__global__ __launch_bounds__(1024) void scan_part1(int n) {
    int i = blockIdx.x * 1024 + threadIdx.x;
    int v = (i < n) ? g_counts[i] : 0;
    int lane = threadIdx.x & 31, wid = threadIdx.x >> 5;

    int x = v;
    #pragma unroll
    for (int o = 1; o < 32; o <<= 1) {
        int t = __shfl_up_sync(0xffffffffu, x, o);
        if (lane >= o) x += t;
    }
    __shared__ int wsum[32];
    if (lane == 31) wsum[wid] = x;
    __syncthreads();
    if (wid == 0) {
        int ws = wsum[lane];
        #pragma unroll
        for (int o = 1; o < 32; o <<= 1) {
            int t = __shfl_up_sync(0xffffffffu, ws, o);
            if (lane >= o) ws += t;
        }
        wsum[lane] = ws;
    }
    __syncthreads();
    int incl = x + (wid > 0 ? wsum[wid - 1] : 0);
    if (i < n) g_offsets[i] = incl - v;              // local exclusive
    if (threadIdx.x == 1023) g_bsums[blockIdx.x] = incl;
}

__global__ void scan_part2(int nb, int n) {
    __shared__ int ws[2];
    int lane = threadIdx.x & 31, w = threadIdx.x >> 5;
    int v = (threadIdx.x < nb) ? g_bsums[threadIdx.x] : 0;
    int x = v;
    #pragma unroll
    for (int o = 1; o < 32; o <<= 1) {
        int t = __shfl_up_sync(0xffffffffu, x, o);
        if (lane >= o) x += t;
    }
    if (lane == 31) ws[w] = x;
    __syncthreads();
    int incl = x + ((w == 1) ? ws[0] : 0);
    if (threadIdx.x < nb) g_bsums[threadIdx.x] = incl - v;   // exclusive
    if (threadIdx.x == nb - 1) g_offsets[n] = incl;
}

__global__ __launch_bounds__(1024) void scan_part3(int n) {
    int i = blockIdx.x * 1024 + threadIdx.x;
    if (i < n) {
        int off = g_offsets[i] + g_bsums[blockIdx.x];
        g_offsets[i] = off;
        g_cursor[i]  = off;
    }
}

// CSR fill straight from raw edges
__global__ void fill_kernel(const void* __restrict__ raw, int E) {
    int i = blockIdx.x * blockDim.x + threadIdx.x;
    if (i >= E) return;
    int s, d;
    if (g_is64) {
        const long long* p = (const long long*)raw;
        s = (int)p[i]; d = (int)p[E + i];
    } else {
        const int* p = (const int*)raw;
        s = p[i]; d = p[E + i];
    }
    int pos = atomicAdd(&g_cursor[d], 1);
    g_src_sorted[pos] = s;
}

// ---------------- fp16 tensor-core GEMM: Ch = half(dis[m] * (A @ Bt^T)) ----------------
#define LDH 40   // padded row (halves): bank = (20*row + word) % 32, conflict-free

template<bool A_HALF>
__global__ __launch_bounds__(256) void hgemm_kernel(
    const void* __restrict__ Ain, const __half* __restrict__ Bt,
    __half* __restrict__ Ch, const float* __restrict__ dis,
    int M, int N, int K)
{
    __shared__ __half As[128][LDH];   // [m][k]
    __shared__ __half Bs[128][LDH];   // [n][k]

    const int tid  = threadIdx.x;
    const int lane = tid & 31;
    const int w    = tid >> 5;
    const int wm   = (w & 3) * 32;
    const int wn   = (w >> 2) * 64;
    const int bm   = blockIdx.y * 128;
    const int bn   = blockIdx.x * 128;
    const int r    = lane >> 2;
    const int c    = lane & 3;

    float acc[2][8][4];
    #pragma unroll
    for (int i = 0; i < 2; i++)
        #pragma unroll
        for (int j = 0; j < 8; j++)
            #pragma unroll
            for (int q = 0; q < 4; q++) acc[i][j][q] = 0.f;

    const int sr = tid & 127;
    const int sq = tid >> 7;            // 0/1 -> k-offset sq*16
    const int amg = bm + sr;
    const bool arow_ok = (amg < M);

    const float* Af = (const float*)Ain;
    const __half* Ah = (const __half*)Ain;

    float4 fa[4];
    uint4  ha[2];
    uint4  hb[2];

    const int ntiles = K / 32;

    {
        int k0 = sq * 16;
        if (A_HALF) {
            if (arow_ok) {
                ha[0] = *(const uint4*)&Ah[(long long)amg * K + k0];
                ha[1] = *(const uint4*)&Ah[(long long)amg * K + k0 + 8];
            } else { ha[0] = make_uint4(0,0,0,0); ha[1] = make_uint4(0,0,0,0); }
        } else {
            #pragma unroll
            for (int i = 0; i < 4; i++)
                fa[i] = arow_ok ? *(const float4*)&Af[(long long)amg * K + k0 + i * 4]
                                : make_float4(0.f,0.f,0.f,0.f);
        }
        hb[0] = *(const uint4*)&Bt[(long long)(bn + sr) * K + k0];
        hb[1] = *(const uint4*)&Bt[(long long)(bn + sr) * K + k0 + 8];
    }

    for (int kt = 0; kt < ntiles; kt++) {
        __syncthreads();
        if (A_HALF) {
            *(uint4*)&As[sr][sq * 16]     = ha[0];
            *(uint4*)&As[sr][sq * 16 + 8] = ha[1];
        } else {
            __half2 h8[8];
            h8[0] = __floats2half2_rn(fa[0].x, fa[0].y);
            h8[1] = __floats2half2_rn(fa[0].z, fa[0].w);
            h8[2] = __floats2half2_rn(fa[1].x, fa[1].y);
            h8[3] = __floats2half2_rn(fa[1].z, fa[1].w);
            h8[4] = __floats2half2_rn(fa[2].x, fa[2].y);
            h8[5] = __floats2half2_rn(fa[2].z, fa[2].w);
            h8[6] = __floats2half2_rn(fa[3].x, fa[3].y);
            h8[7] = __floats2half2_rn(fa[3].z, fa[3].w);
            *(uint4*)&As[sr][sq * 16]     = *(uint4*)&h8[0];
            *(uint4*)&As[sr][sq * 16 + 8] = *(uint4*)&h8[4];
        }
        *(uint4*)&Bs[sr][sq * 16]     = hb[0];
        *(uint4*)&Bs[sr][sq * 16 + 8] = hb[1];
        __syncthreads();

        if (kt + 1 < ntiles) {
            int k0 = (kt + 1) * 32 + sq * 16;
            if (A_HALF) {
                if (arow_ok) {
                    ha[0] = *(const uint4*)&Ah[(long long)amg * K + k0];
                    ha[1] = *(const uint4*)&Ah[(long long)amg * K + k0 + 8];
                }
            } else {
                #pragma unroll
                for (int i = 0; i < 4; i++)
                    fa[i] = arow_ok ? *(const float4*)&Af[(long long)amg * K + k0 + i * 4]
                                    : make_float4(0.f,0.f,0.f,0.f);
            }
            hb[0] = *(const uint4*)&Bt[(long long)(bn + sr) * K + k0];
            hb[1] = *(const uint4*)&Bt[(long long)(bn + sr) * K + k0 + 8];
        }

        #pragma unroll
        for (int ks = 0; ks < 2; ks++) {
            int kk = ks * 16;
            unsigned af[2][4];
            #pragma unroll
            for (int tm = 0; tm < 2; tm++) {
                int mb = wm + tm * 16;
                af[tm][0] = *(const unsigned*)&As[mb + r    ][kk + c * 2    ];
                af[tm][1] = *(const unsigned*)&As[mb + r + 8][kk + c * 2    ];
                af[tm][2] = *(const unsigned*)&As[mb + r    ][kk + c * 2 + 8];
                af[tm][3] = *(const unsigned*)&As[mb + r + 8][kk + c * 2 + 8];
            }
            unsigned bf[8][2];
            #pragma unroll
            for (int tn = 0; tn < 8; tn++) {
                int nb = wn + tn * 8 + r;
                bf[tn][0] = *(const unsigned*)&Bs[nb][kk + c * 2    ];
                bf[tn][1] = *(const unsigned*)&Bs[nb][kk + c * 2 + 8];
            }
            #pragma unroll
            for (int tm = 0; tm < 2; tm++)
                #pragma unroll
                for (int tn = 0; tn < 8; tn++) {
                    asm volatile(
                        "mma.sync.aligned.m16n8k16.row.col.f32.f16.f16.f32 "
                        "{%0,%1,%2,%3}, {%4,%5,%6,%7}, {%8,%9}, {%0,%1,%2,%3};"
                        : "+f"(acc[tm][tn][0]), "+f"(acc[tm][tn][1]),
                          "+f"(acc[tm][tn][2]), "+f"(acc[tm][tn][3])
                        : "r"(af[tm][0]), "r"(af[tm][1]),
                          "r"(af[tm][2]), "r"(af[tm][3]),
                          "r"(bf[tn][0]), "r"(bf[tn][1]));
                }
        }
    }

    #pragma unroll
    for (int tm = 0; tm < 2; tm++) {
        int row0 = bm + wm + tm * 16 + r;
        int row1 = row0 + 8;
        float s0 = (row0 < M) ? dis[row0] : 0.f;
        float s1 = (row1 < M) ? dis[row1] : 0.f;
        #pragma unroll
        for (int tn = 0; tn < 8; tn++) {
            int col = bn + wn + tn * 8 + c * 2;
            if (row0 < M) {
                __half2 hv = __floats2half2_rn(acc[tm][tn][0] * s0,
                                               acc[tm][tn][1] * s0);
                *(__half2*)&Ch[(long long)row0 * N + col] = hv;
            }
            if (row1 < M) {
                __half2 hv = __floats2half2_rn(acc[tm][tn][2] * s1,
                                               acc[tm][tn][3] * s1);
                *(__half2*)&Ch[(long long)row1 * N + col] = hv;
            }
        }
    }
}

// ---------------- aggregation (half gathers, pre-scaled) ----------------
// z[i] = f( di * ( hh[i] + sum_{s in N(i)} hh[s] ) + b )   where hh = h*dis
template<int D, bool RELU, bool OUT_HALF>
__global__ __launch_bounds__(256) void agg_half_kernel(
    const __half* __restrict__ HH, void* __restrict__ Zout,
    const float* __restrict__ bias)
{
    constexpr int TPN = D / 4;
    constexpr int NPB = 256 / TPN;
    const int node = blockIdx.x * NPB + threadIdx.x / TPN;
    const int t    = threadIdx.x % TPN;
    if (node >= N_NODES) return;

    const float di = g_dis[node];
    const uint2* Hq = (const uint2*)HH;

    uint2 sv = Hq[(long long)node * TPN + t];
    float2 s0 = __half22float2(*(__half2*)&sv.x);
    float2 s1 = __half22float2(*(__half2*)&sv.y);
    float a0 = s0.x, a1 = s0.y, a2 = s1.x, a3 = s1.y;

    int e   = g_offsets[node];
    int end = g_offsets[node + 1];

    for (; e + 4 <= end; e += 4) {
        int n0 = g_src_sorted[e + 0];
        int n1 = g_src_sorted[e + 1];
        int n2 = g_src_sorted[e + 2];
        int n3 = g_src_sorted[e + 3];
        uint2 v0 = Hq[(long long)n0 * TPN + t];
        uint2 v1 = Hq[(long long)n1 * TPN + t];
        uint2 v2 = Hq[(long long)n2 * TPN + t];
        uint2 v3 = Hq[(long long)n3 * TPN + t];
        float2 p;
        p = __half22float2(*(__half2*)&v0.x); a0 += p.x; a1 += p.y;
        p = __half22float2(*(__half2*)&v0.y); a2 += p.x; a3 += p.y;
        p = __half22float2(*(__half2*)&v1.x); a0 += p.x; a1 += p.y;
        p = __half22float2(*(__half2*)&v1.y); a2 += p.x; a3 += p.y;
        p = __half22float2(*(__half2*)&v2.x); a0 += p.x; a1 += p.y;
        p = __half22float2(*(__half2*)&v2.y); a2 += p.x; a3 += p.y;
        p = __half22float2(*(__half2*)&v3.x); a0 += p.x; a1 += p.y;
        p = __half22float2(*(__half2*)&v3.y); a2 += p.x; a3 += p.y;
    }
    for (; e < end; e++) {
        int s = g_src_sorted[e];
        uint2 v = Hq[(long long)s * TPN + t];
        float2 p;
        p = __half22float2(*(__half2*)&v.x); a0 += p.x; a1 += p.y;
        p = __half22float2(*(__half2*)&v.y); a2 += p.x; a3 += p.y;
    }

    const float4 bv = *(const float4*)&bias[t * 4];
    float o0 = a0 * di + bv.x;
    float o1 = a1 * di + bv.y;
    float o2 = a2 * di + bv.z;
    float o3 = a3 * di + bv.w;
    if (RELU) {
        o0 = fmaxf(o0, 0.f); o1 = fmaxf(o1, 0.f);
        o2 = fmaxf(o2, 0.f); o3 = fmaxf(o3, 0.f);
    }
    if (OUT_HALF) {
        __half2 h0 = __floats2half2_rn(o0, o1);
        __half2 h1 = __floats2half2_rn(o2, o3);
        uint2 st; st.x = *(unsigned*)&h0; st.y = *(unsigned*)&h1;
        *(uint2*)&((__half*)Zout)[(long long)node * D + t * 4] = st;
    } else {
        float4 out = make_float4(o0, o1, o2, o3);
        *(float4*)&((float*)Zout)[(long long)node * D + t * 4] = out;
    }
}

// ---------------- decode: y[e] = dot(z2[a], z2[b]) ----------------
__global__ void decode_kernel(const void* __restrict__ eli_raw,
                              const float* __restrict__ Z,
                              float* __restrict__ y, int EL)
{
    int gw   = (blockIdx.x * blockDim.x + threadIdx.x) >> 5;
    int lane = threadIdx.x & 31;
    if (gw >= EL) return;
    int a, b;
    if (g_is64) {
        const long long* p = (const long long*)eli_raw;
        a = (int)p[gw]; b = (int)p[EL + gw];
    } else {
        const int* p = (const int*)eli_raw;
        a = p[gw]; b = p[EL + gw];
    }
    float4 za = *(const float4*)&Z[(long long)a * 128 + lane * 4];
    float4 zb = *(const float4*)&Z[(long long)b * 128 + lane * 4];
    float s = za.x * zb.x + za.y * zb.y + za.z * zb.z + za.w * zb.w;
    #pragma unroll
    for (int o = 16; o; o >>= 1) s += __shfl_down_sync(0xffffffffu, s, o);
    if (lane == 0) y[gw] = s;
}

// ---------------- launch ----------------
extern "C" void kernel_launch(void* const* d_in, const int* in_sizes, int n_in,
                              void* d_out, int out_size)
{
    const float* x   = (const float*)d_in[0];
    const void*  ei  = d_in[1];
    const void*  eli = d_in[2];
    const float* W1  = (const float*)d_in[3];
    const float* b1  = (const float*)d_in[4];
    const float* W2  = (const float*)d_in[5];
    const float* b2  = (const float*)d_in[6];
    float*       y   = (float*)d_out;

    const int E  = in_sizes[1] / 2;
    const int EL = in_sizes[2] / 2;

    __half *hh1p, *z1hp, *hh2p, *w1tp, *w2tp;
    float  *z2p, *disp;
    cudaGetSymbolAddress((void**)&hh1p, g_hh1);
    cudaGetSymbolAddress((void**)&z1hp, g_z1h);
    cudaGetSymbolAddress((void**)&hh2p, g_hh2);
    cudaGetSymbolAddress((void**)&z2p,  g_z2);
    cudaGetSymbolAddress((void**)&disp, g_dis);
    cudaGetSymbolAddress((void**)&w1tp, g_w1t);
    cudaGetSymbolAddress((void**)&w2tp, g_w2t);

    const int TB = 256;
    // 0: fused init (weights + zero counts + detect)
    init_kernel<<<(D_IN * D_H + TB - 1) / TB, TB>>>(W1, W2, (const int*)ei);
    // 1: degree count from raw
    count_kernel<<<(E + TB - 1) / TB, TB>>>(ei, E);
    // 2: dis
    dis_kernel<<<(N_NODES + TB - 1) / TB, TB>>>();
    // 3: layer-1 GEMM (profiled slot)
    {
        dim3 grid(D_H / 128, (N_NODES + 127) / 128);
        hgemm_kernel<false><<<grid, 256>>>(x, w1tp, hh1p, disp, N_NODES, D_H, D_IN);
    }
    // 4-6: scan
    scan_part1<<<SCAN_B, 1024>>>(N_NODES);
    scan_part2<<<1, 64>>>(SCAN_B, N_NODES);
    scan_part3<<<SCAN_B, 1024>>>(N_NODES);
    // 7: CSR fill from raw
    fill_kernel<<<(E + TB - 1) / TB, TB>>>(ei, E);
    // 8: layer-1 aggregation -> z1 (half)
    agg_half_kernel<D_H, true, true><<<(N_NODES + 3) / 4, 256>>>(hh1p, z1hp, b1);
    // 9: layer-2 GEMM
    {
        dim3 grid(D_OUT / 128, (N_NODES + 127) / 128);
        hgemm_kernel<true><<<grid, 256>>>(z1hp, w2tp, hh2p, disp, N_NODES, D_OUT, D_H);
    }
    // 10: layer-2 aggregation -> z2 (fp32)
    agg_half_kernel<D_OUT, false, false><<<(N_NODES + 7) / 8, 256>>>(hh2p, z2p, b2);
    // 11: decode
    decode_kernel<<<(EL * 32 + TB - 1) / TB, TB>>>(eli, z2p, y, EL);
}